// round 3
// baseline (speedup 1.0000x reference)
#include <cuda_runtime.h>
#include <cuda_bf16.h>
#include <mma.h>

using namespace nvcuda;

constexpr int DMAX  = 128;
constexpr int NMAX  = 50000;

__device__ float g_P[(size_t)NMAX * DMAX];
__device__ float g_pooled[(size_t)NMAX * DMAX];
__device__ float g_x1[(size_t)NMAX * DMAX];
__device__ float g_x2[(size_t)NMAX * DMAX];

// ---------------------------------------------------------------------------
// TF32 tensor-core GEMM with 3-term split (near-fp32 accuracy):
//   C[n][j] = (RES ? R : 0) + A @ W + bias
// A: Nrows x 128, W: 128 x 128 (row-major k x n).
// CTA tile 128x128, 8 warps (4M x 2N), warp tile 32x64 (2x4 wmma 16x16x8).
// Split: A = Ah + Al, W = Wh + Wl; acc += Ah*Wh + Al*Wh + Ah*Wl.
// k-chunk = 16 so all staging fits in STATIC shared memory (<48KB):
//   sAh/sAl: 128 x 20 floats each, sBh/sBl: 16 x 132 floats each = 37,376 B.
// Epilogue reuses the same smem as a 64 x 132 C-stage, two halves.
// ---------------------------------------------------------------------------
constexpr int LDA = 20;   // 16 + 4 pad
constexpr int LDB = 132;  // 128 + 4 pad
constexpr int LDC = 132;
constexpr int OFF_AH = 0;
constexpr int OFF_AL = 128 * LDA;                 // 2560
constexpr int OFF_BH = 2 * 128 * LDA;             // 5120
constexpr int OFF_BL = OFF_BH + 16 * LDB;         // 7232
constexpr int SMEM_FLOATS = OFF_BL + 16 * LDB;    // 9344 floats = 37,376 B

__device__ __forceinline__ void split_tf32(float v, float& h, float& l) {
    h = wmma::__float_to_tf32(v);
    l = wmma::__float_to_tf32(v - h);
}

template <bool RES>
__global__ __launch_bounds__(256) void gemm_tf32_kernel(
        const float* __restrict__ A, const float* __restrict__ W,
        const float* __restrict__ bias, const float* __restrict__ R,
        float* __restrict__ C, int Nrows) {
    __shared__ float smem[SMEM_FLOATS];
    float* sAh = smem + OFF_AH;
    float* sAl = smem + OFF_AL;
    float* sBh = smem + OFF_BH;
    float* sBl = smem + OFF_BL;

    const int tid = threadIdx.x;
    const int warp = tid >> 5;
    const int wm = warp >> 1;        // 0..3 -> rows [wm*32, wm*32+32)
    const int wn = warp & 1;         // 0..1 -> cols [wn*64, wn*64+64)
    const int row0 = blockIdx.x * 128;

    wmma::fragment<wmma::accumulator, 16, 16, 8, float> acc[2][4];
#pragma unroll
    for (int i = 0; i < 2; i++)
#pragma unroll
        for (int j = 0; j < 4; j++) wmma::fill_fragment(acc[i][j], 0.0f);

#pragma unroll 1
    for (int k0 = 0; k0 < 128; k0 += 16) {
        // A chunk: 128 rows x 16 cols = 512 float4, 2 per thread.
#pragma unroll
        for (int it = 0; it < 2; it++) {
            int idx = tid + it * 256;
            int r = idx >> 2;          // 0..127
            int c4 = idx & 3;          // float4 col within 16
            float4 v = make_float4(0.f, 0.f, 0.f, 0.f);
            if (row0 + r < Nrows)
                v = reinterpret_cast<const float4*>(A + (size_t)(row0 + r) * 128 + k0)[c4];
            float* ph = sAh + r * LDA + c4 * 4;
            float* pl = sAl + r * LDA + c4 * 4;
            split_tf32(v.x, ph[0], pl[0]);
            split_tf32(v.y, ph[1], pl[1]);
            split_tf32(v.z, ph[2], pl[2]);
            split_tf32(v.w, ph[3], pl[3]);
        }
        // W chunk: 16 rows x 128 cols = 512 float4, 2 per thread.
#pragma unroll
        for (int it = 0; it < 2; it++) {
            int idx = tid + it * 256;
            int r = idx >> 5;          // 0..15
            int c4 = idx & 31;
            float4 v = reinterpret_cast<const float4*>(W + (size_t)(k0 + r) * 128)[c4];
            float* ph = sBh + r * LDB + c4 * 4;
            float* pl = sBl + r * LDB + c4 * 4;
            split_tf32(v.x, ph[0], pl[0]);
            split_tf32(v.y, ph[1], pl[1]);
            split_tf32(v.z, ph[2], pl[2]);
            split_tf32(v.w, ph[3], pl[3]);
        }
        __syncthreads();

#pragma unroll
        for (int kk = 0; kk < 2; kk++) {
            wmma::fragment<wmma::matrix_a, 16, 16, 8, wmma::precision::tf32, wmma::row_major> ah[2], al[2];
#pragma unroll
            for (int i = 0; i < 2; i++) {
                wmma::load_matrix_sync(ah[i], sAh + (wm * 32 + i * 16) * LDA + kk * 8, LDA);
                wmma::load_matrix_sync(al[i], sAl + (wm * 32 + i * 16) * LDA + kk * 8, LDA);
            }
#pragma unroll
            for (int j = 0; j < 4; j++) {
                wmma::fragment<wmma::matrix_b, 16, 16, 8, wmma::precision::tf32, wmma::row_major> bh, bl;
                wmma::load_matrix_sync(bh, sBh + (kk * 8) * LDB + wn * 64 + j * 16, LDB);
                wmma::load_matrix_sync(bl, sBl + (kk * 8) * LDB + wn * 64 + j * 16, LDB);
#pragma unroll
                for (int i = 0; i < 2; i++) {
                    wmma::mma_sync(acc[i][j], ah[i], bh, acc[i][j]);
                    wmma::mma_sync(acc[i][j], al[i], bh, acc[i][j]);
                    wmma::mma_sync(acc[i][j], ah[i], bl, acc[i][j]);
                }
            }
        }
        __syncthreads();
    }

    // Epilogue in two 64-row halves (reuse smem as sC: 64 x 132 floats).
    float* sC = smem;
#pragma unroll
    for (int half = 0; half < 2; half++) {
        __syncthreads();
        if ((wm >> 1) == half) {
            int rbase = (wm & 1) * 32;
#pragma unroll
            for (int i = 0; i < 2; i++)
#pragma unroll
                for (int j = 0; j < 4; j++)
                    wmma::store_matrix_sync(sC + (rbase + i * 16) * LDC + wn * 64 + j * 16,
                                            acc[i][j], LDC, wmma::mem_row_major);
        }
        __syncthreads();
#pragma unroll
        for (int it = 0; it < 8; it++) {
            int idx = tid + it * 256;     // 0..2047
            int r = idx >> 5;             // 0..63
            int c4 = idx & 31;
            int grow = row0 + half * 64 + r;
            if (grow < Nrows) {
                float4 o = *reinterpret_cast<float4*>(sC + r * LDC + c4 * 4);
                float4 bv = reinterpret_cast<const float4*>(bias)[c4];
                o.x += bv.x; o.y += bv.y; o.z += bv.z; o.w += bv.w;
                if (RES) {
                    float4 rv = reinterpret_cast<const float4*>(R + (size_t)grow * 128)[c4];
                    o.x += rv.x; o.y += rv.y; o.z += rv.z; o.w += rv.w;
                }
                reinterpret_cast<float4*>(C + (size_t)grow * 128)[c4] = o;
            }
        }
    }
}

// ---------------------------------------------------------------------------
// Edge kernel with 8-deep software pipeline on the P-row gather.
// Each warp: 32 contiguous edges. Per-lane coalesced preload of edge
// descriptors, shfl-broadcast per iteration, run-max in registers, atomicMax
// flush on segment change (valid for nonnegative floats; pooled init 0).
// ---------------------------------------------------------------------------
__device__ __forceinline__ void flush_max(float* pooled, int seg, int lane, float4 v) {
    if (seg < 0) return;
    int* p = reinterpret_cast<int*>(pooled + (size_t)seg * 128 + lane * 4);
    if (v.x > 0.f) atomicMax(p + 0, __float_as_int(v.x));
    if (v.y > 0.f) atomicMax(p + 1, __float_as_int(v.y));
    if (v.z > 0.f) atomicMax(p + 2, __float_as_int(v.z));
    if (v.w > 0.f) atomicMax(p + 3, __float_as_int(v.w));
}

constexpr int PF = 8;   // pipeline depth (power of 2)

__global__ __launch_bounds__(256) void edge_kernel(
        const float4* __restrict__ P4, const float4* __restrict__ ai,
        const int* __restrict__ nb, const int* __restrict__ seg,
        const float* __restrict__ Wba, float* __restrict__ pooled, int E) {
    __shared__ float4 wsh[128];
    const int tid = threadIdx.x;
    if (tid < 128) wsh[tid] = reinterpret_cast<const float4*>(Wba)[tid];
    __syncthreads();

    const int lane = tid & 31;
    const int warp = tid >> 5;
    const float4 w0 = wsh[lane];
    const float4 w1 = wsh[32 + lane];
    const float4 w2 = wsh[64 + lane];
    const float4 w3 = wsh[96 + lane];

    const int base = (blockIdx.x * (blockDim.x >> 5) + warp) * 32;
    if (base >= E) return;
    const int cnt = min(32, E - base);

    int my_n = 0, my_s = -1;
    float4 my_a = make_float4(0.f, 0.f, 0.f, 0.f);
    if (lane < cnt) {
        my_n = __ldg(nb + base + lane);
        my_s = __ldg(seg + base + lane);
        my_a = __ldg(ai + base + lane);
    }

    float4 pbuf[PF];
#pragma unroll
    for (int i = 0; i < PF; i++) {
        int n = __shfl_sync(0xFFFFFFFFu, my_n, i);
        pbuf[i] = (i < cnt) ? __ldg(P4 + (size_t)n * 32 + lane)
                            : make_float4(0.f, 0.f, 0.f, 0.f);
    }

    float4 vmax = make_float4(0.f, 0.f, 0.f, 0.f);
    int cur = -1;

#pragma unroll
    for (int i = 0; i < 32; i++) {
        if (i >= cnt) break;
        float4 p = pbuf[i & (PF - 1)];
        float ax = __shfl_sync(0xFFFFFFFFu, my_a.x, i);
        float ay = __shfl_sync(0xFFFFFFFFu, my_a.y, i);
        float az = __shfl_sync(0xFFFFFFFFu, my_a.z, i);
        float aw = __shfl_sync(0xFFFFFFFFu, my_a.w, i);
        int   s  = __shfl_sync(0xFFFFFFFFu, my_s, i);

        float4 h;
        h.x = fmaxf(fmaf(ax, w0.x, fmaf(ay, w1.x, fmaf(az, w2.x, fmaf(aw, w3.x, p.x)))), 0.f);
        h.y = fmaxf(fmaf(ax, w0.y, fmaf(ay, w1.y, fmaf(az, w2.y, fmaf(aw, w3.y, p.y)))), 0.f);
        h.z = fmaxf(fmaf(ax, w0.z, fmaf(ay, w1.z, fmaf(az, w2.z, fmaf(aw, w3.z, p.z)))), 0.f);
        h.w = fmaxf(fmaf(ax, w0.w, fmaf(ay, w1.w, fmaf(az, w2.w, fmaf(aw, w3.w, p.w)))), 0.f);

        if (s != cur) {               // warp-uniform
            flush_max(pooled, cur, lane, vmax);
            cur = s;
            vmax = h;
        } else {
            vmax.x = fmaxf(vmax.x, h.x);
            vmax.y = fmaxf(vmax.y, h.y);
            vmax.z = fmaxf(vmax.z, h.z);
            vmax.w = fmaxf(vmax.w, h.w);
        }

        int ip = i + PF;
        if (ip < cnt) {
            int n = __shfl_sync(0xFFFFFFFFu, my_n, ip);
            pbuf[i & (PF - 1)] = __ldg(P4 + (size_t)n * 32 + lane);
        }
    }
    flush_max(pooled, cur, lane, vmax);
}

// ---------------------------------------------------------------------------
__global__ void final_kernel(const float* __restrict__ x,
                             const float* __restrict__ Wf,
                             const float* __restrict__ bf,
                             float* __restrict__ out, int N) {
    int gwarp = (blockIdx.x * blockDim.x + threadIdx.x) >> 5;
    int lane = threadIdx.x & 31;
    if (gwarp >= N) return;
    float4 xv = reinterpret_cast<const float4*>(x + (size_t)gwarp * 128)[lane];
    float4 wv = reinterpret_cast<const float4*>(Wf)[lane];
    float s = xv.x * wv.x + xv.y * wv.y + xv.z * wv.z + xv.w * wv.w;
#pragma unroll
    for (int o = 16; o; o >>= 1) s += __shfl_xor_sync(0xFFFFFFFFu, s, o);
    if (lane == 0) out[gwarp] = s + bf[0];
}

// ---------------------------------------------------------------------------
extern "C" void kernel_launch(void* const* d_in, const int* in_sizes, int n_in,
                              void* d_out, int out_size) {
    const float* interpolated = (const float*)d_in[0];
    const float* add_info     = (const float*)d_in[1];
    const int*   nb           = (const int*)d_in[2];
    const int*   seg          = (const int*)d_in[3];
    const float* Wb0 = (const float*)d_in[4];
    const float* bb0 = (const float*)d_in[5];
    const float* Wo0 = (const float*)d_in[6];
    const float* bo0 = (const float*)d_in[7];
    const float* Wb1 = (const float*)d_in[8];
    const float* bb1 = (const float*)d_in[9];
    const float* Wo1 = (const float*)d_in[10];
    const float* bo1 = (const float*)d_in[11];
    const float* Wf  = (const float*)d_in[12];
    const float* bf  = (const float*)d_in[13];

    const int N = in_sizes[0] / 128;
    const int E = in_sizes[2];

    float *P, *pooled, *x1, *x2;
    cudaGetSymbolAddress((void**)&P,      g_P);
    cudaGetSymbolAddress((void**)&pooled, g_pooled);
    cudaGetSymbolAddress((void**)&x1,     g_x1);
    cudaGetSymbolAddress((void**)&x2,     g_x2);

    const int gemmGrid = (N + 127) / 128;
    const int edgeGrid = (E + 256 - 1) / 256;   // 8 warps/CTA, 32 edges/warp
    const size_t poolBytes = (size_t)N * 128 * sizeof(float);
    const float4* ai = (const float4*)add_info;

    // ---- Block 0 ----
    cudaMemsetAsync(pooled, 0, poolBytes);
    gemm_tf32_kernel<false><<<gemmGrid, 256>>>(interpolated, Wb0, bb0, nullptr, P, N);
    edge_kernel<<<edgeGrid, 256>>>((const float4*)P, ai, nb, seg, Wb0 + 128 * 128, pooled, E);
    gemm_tf32_kernel<true><<<gemmGrid, 256>>>(pooled, Wo0, bo0, interpolated, x1, N);

    // ---- Block 1 ----
    cudaMemsetAsync(pooled, 0, poolBytes);
    gemm_tf32_kernel<false><<<gemmGrid, 256>>>(x1, Wb1, bb1, nullptr, P, N);
    edge_kernel<<<edgeGrid, 256>>>((const float4*)P, ai, nb, seg, Wb1 + 128 * 128, pooled, E);
    gemm_tf32_kernel<true><<<gemmGrid, 256>>>(pooled, Wo1, bo1, x1, x2, N);

    // ---- Final projection ----
    final_kernel<<<(N * 32 + 255) / 256, 256>>>(x2, Wf, bf, (float*)d_out, N);
}

// round 4
// speedup vs baseline: 1.8402x; 1.8402x over previous
#include <cuda_runtime.h>
#include <cuda_bf16.h>
#include <mma.h>

using namespace nvcuda;

constexpr int DMAX = 128;
constexpr int NMAX = 50000;

__device__ __nv_bfloat16 g_Pb[(size_t)NMAX * DMAX];   // P in bf16 (halves gather traffic)
__device__ float g_pooled[(size_t)NMAX * DMAX];
__device__ float g_x1[(size_t)NMAX * DMAX];

// ---------------------------------------------------------------------------
// bf16 tensor-core GEMM with 3-term split (near-fp32 accuracy):
//   C[n][j] = (RES ? R : 0) + A @ W + bias       A: Nrows x 128, W: 128 x 128
// Split A = Ah + Al, W = Wh + Wl (bf16); acc += Ah*Wh + Al*Wh + Ah*Wl (fp32 acc).
// CTA tile 128x128, 8 warps (2M x 4N), warp tile 64x32 (4x2 m16n16k16 frags).
// k-chunk 32, static smem ~37.9KB, __launch_bounds__(256,2) => 2 CTA/SM so the
// load/split phase of one CTA overlaps the mma phase of the other.
// Epilogue variants: fp32 out, bf16 out (for P), or fused final dot with Wf.
// ---------------------------------------------------------------------------
constexpr int KC   = 32;
constexpr int LDAB = 40;    // bf16 elems, A tiles (32 + 8 pad, mult of 8)
constexpr int LDBB = 136;   // bf16 elems, B tiles (128 + 8 pad)
constexpr int LDC  = 132;   // fp32 elems, C staging
constexpr int SM_AH = 0;                  // bf16 offsets
constexpr int SM_AL = SM_AH + 128 * LDAB; // 5120
constexpr int SM_BH = SM_AL + 128 * LDAB; // 10240
constexpr int SM_BL = SM_BH + KC * LDBB;  // 14592
constexpr int SMEM_BF16 = SM_BL + KC * LDBB;          // 18944 bf16 = 37,888 B
static_assert(SMEM_BF16 * 2 >= 64 * LDC * 4, "C stage fits");

__device__ __forceinline__ void split_bf16(float v, __nv_bfloat16& h, __nv_bfloat16& l) {
    h = __float2bfloat16(v);
    l = __float2bfloat16(v - __bfloat162float(h));
}

template <bool RES, bool OUT_BF16, bool FINAL>
__global__ __launch_bounds__(256, 2) void gemm_kernel(
        const float* __restrict__ A, const float* __restrict__ W,
        const float* __restrict__ bias, const float* __restrict__ R,
        float* __restrict__ Cf, __nv_bfloat16* __restrict__ Cb,
        const float* __restrict__ Wf, const float* __restrict__ bf,
        float* __restrict__ out, int Nrows) {
    __shared__ __align__(16) char smem_raw[SMEM_BF16 * 2];
    __nv_bfloat16* sb = reinterpret_cast<__nv_bfloat16*>(smem_raw);
    __nv_bfloat16* sAh = sb + SM_AH;
    __nv_bfloat16* sAl = sb + SM_AL;
    __nv_bfloat16* sBh = sb + SM_BH;
    __nv_bfloat16* sBl = sb + SM_BL;
    float* sC = reinterpret_cast<float*>(smem_raw);

    const int tid  = threadIdx.x;
    const int lane = tid & 31;
    const int warp = tid >> 5;
    const int wm = warp >> 2;     // 0..1 : rows [wm*64, +64)
    const int wn = warp & 3;      // 0..3 : cols [wn*32, +32)
    const int row0 = blockIdx.x * 128;

    float4 wfv = make_float4(0.f, 0.f, 0.f, 0.f);
    float bf0 = 0.f;
    if (FINAL) { wfv = reinterpret_cast<const float4*>(Wf)[lane]; bf0 = bf[0]; }

    wmma::fragment<wmma::accumulator, 16, 16, 16, float> acc[4][2];
#pragma unroll
    for (int i = 0; i < 4; i++)
#pragma unroll
        for (int j = 0; j < 2; j++) wmma::fill_fragment(acc[i][j], 0.0f);

#pragma unroll 1
    for (int k0 = 0; k0 < 128; k0 += KC) {
        // A chunk: 128 x 32 floats = 1024 float4, 4/thread -> split to bf16 hi/lo
#pragma unroll
        for (int it = 0; it < 4; it++) {
            int idx = tid + it * 256;
            int r = idx >> 3;          // 0..127
            int c4 = idx & 7;          // float4 col within 32
            float4 v = make_float4(0.f, 0.f, 0.f, 0.f);
            if (row0 + r < Nrows)
                v = reinterpret_cast<const float4*>(A + (size_t)(row0 + r) * 128 + k0)[c4];
            __nv_bfloat16 h[4], l[4];
            split_bf16(v.x, h[0], l[0]); split_bf16(v.y, h[1], l[1]);
            split_bf16(v.z, h[2], l[2]); split_bf16(v.w, h[3], l[3]);
            *reinterpret_cast<uint2*>(sAh + r * LDAB + c4 * 4) = *reinterpret_cast<uint2*>(h);
            *reinterpret_cast<uint2*>(sAl + r * LDAB + c4 * 4) = *reinterpret_cast<uint2*>(l);
        }
        // W chunk: 32 x 128 floats = 1024 float4, 4/thread
#pragma unroll
        for (int it = 0; it < 4; it++) {
            int idx = tid + it * 256;
            int r = idx >> 5;          // 0..31
            int c4 = idx & 31;
            float4 v = reinterpret_cast<const float4*>(W + (size_t)(k0 + r) * 128)[c4];
            __nv_bfloat16 h[4], l[4];
            split_bf16(v.x, h[0], l[0]); split_bf16(v.y, h[1], l[1]);
            split_bf16(v.z, h[2], l[2]); split_bf16(v.w, h[3], l[3]);
            *reinterpret_cast<uint2*>(sBh + r * LDBB + c4 * 4) = *reinterpret_cast<uint2*>(h);
            *reinterpret_cast<uint2*>(sBl + r * LDBB + c4 * 4) = *reinterpret_cast<uint2*>(l);
        }
        __syncthreads();

#pragma unroll
        for (int ks = 0; ks < 2; ks++) {
            const int koff = ks * 16;
            wmma::fragment<wmma::matrix_b, 16, 16, 16, __nv_bfloat16, wmma::row_major> bh[2], bl[2];
#pragma unroll
            for (int j = 0; j < 2; j++) {
                wmma::load_matrix_sync(bh[j], sBh + koff * LDBB + wn * 32 + j * 16, LDBB);
                wmma::load_matrix_sync(bl[j], sBl + koff * LDBB + wn * 32 + j * 16, LDBB);
            }
#pragma unroll
            for (int i = 0; i < 4; i++) {
                wmma::fragment<wmma::matrix_a, 16, 16, 16, __nv_bfloat16, wmma::row_major> ah, al;
                wmma::load_matrix_sync(ah, sAh + (wm * 64 + i * 16) * LDAB + koff, LDAB);
                wmma::load_matrix_sync(al, sAl + (wm * 64 + i * 16) * LDAB + koff, LDAB);
#pragma unroll
                for (int j = 0; j < 2; j++) {
                    wmma::mma_sync(acc[i][j], ah, bh[j], acc[i][j]);
                    wmma::mma_sync(acc[i][j], al, bh[j], acc[i][j]);
                    wmma::mma_sync(acc[i][j], ah, bl[j], acc[i][j]);
                }
            }
        }
        __syncthreads();
    }

    // Epilogue in two 64-row halves, staged through smem (reused as sC).
#pragma unroll
    for (int half = 0; half < 2; half++) {
        __syncthreads();
        if (wm == half) {
#pragma unroll
            for (int i = 0; i < 4; i++)
#pragma unroll
                for (int j = 0; j < 2; j++)
                    wmma::store_matrix_sync(sC + (i * 16) * LDC + wn * 32 + j * 16,
                                            acc[i][j], LDC, wmma::mem_row_major);
        }
        __syncthreads();
#pragma unroll
        for (int it = 0; it < 8; it++) {
            int idx = tid + it * 256;
            int r = idx >> 5;            // 0..63, warp-uniform
            int c4 = idx & 31;           // == lane
            int grow = row0 + half * 64 + r;
            if (grow < Nrows) {
                float4 o = *reinterpret_cast<float4*>(sC + r * LDC + c4 * 4);
                float4 bv = reinterpret_cast<const float4*>(bias)[c4];
                o.x += bv.x; o.y += bv.y; o.z += bv.z; o.w += bv.w;
                if (RES) {
                    float4 rv = reinterpret_cast<const float4*>(R + (size_t)grow * 128)[c4];
                    o.x += rv.x; o.y += rv.y; o.z += rv.z; o.w += rv.w;
                }
                if (FINAL) {
                    float s = o.x * wfv.x + o.y * wfv.y + o.z * wfv.z + o.w * wfv.w;
#pragma unroll
                    for (int off = 16; off; off >>= 1)
                        s += __shfl_xor_sync(0xFFFFFFFFu, s, off);
                    if (lane == 0) out[grow] = s + bf0;
                } else if (OUT_BF16) {
                    __nv_bfloat16 b4[4];
                    b4[0] = __float2bfloat16(o.x); b4[1] = __float2bfloat16(o.y);
                    b4[2] = __float2bfloat16(o.z); b4[3] = __float2bfloat16(o.w);
                    reinterpret_cast<uint2*>(Cb + (size_t)grow * 128)[c4] =
                        *reinterpret_cast<uint2*>(b4);
                } else {
                    reinterpret_cast<float4*>(Cf + (size_t)grow * 128)[c4] = o;
                }
            }
        }
    }
}

// ---------------------------------------------------------------------------
// Edge kernel: bf16 P gather (256B/row), 8-deep pipelined; per-edge uniform
// loads of seg/nb/add_info (hardware broadcast); run-max in registers with
// atomicMax flush on segment change (valid: relu >= 0, pooled init 0).
// ---------------------------------------------------------------------------
__device__ __forceinline__ void flush_max(float* pooled, int seg, int lane, float4 v) {
    if (seg < 0) return;
    int* p = reinterpret_cast<int*>(pooled + (size_t)seg * 128 + lane * 4);
    if (v.x > 0.f) atomicMax(p + 0, __float_as_int(v.x));
    if (v.y > 0.f) atomicMax(p + 1, __float_as_int(v.y));
    if (v.z > 0.f) atomicMax(p + 2, __float_as_int(v.z));
    if (v.w > 0.f) atomicMax(p + 3, __float_as_int(v.w));
}

constexpr int PF = 8;

__global__ __launch_bounds__(256) void edge_kernel(
        const uint2* __restrict__ P2,      // N x 32 uint2 (bf16 rows, 256B)
        const float4* __restrict__ ai,
        const int* __restrict__ nb, const int* __restrict__ seg,
        const float* __restrict__ Wba, float* __restrict__ pooled, int E) {
    __shared__ float4 wsh[128];
    const int tid = threadIdx.x;
    if (tid < 128) wsh[tid] = reinterpret_cast<const float4*>(Wba)[tid];
    __syncthreads();

    const int lane = tid & 31;
    const int warp = tid >> 5;
    const float4 w0 = wsh[lane];
    const float4 w1 = wsh[32 + lane];
    const float4 w2 = wsh[64 + lane];
    const float4 w3 = wsh[96 + lane];

    const int base = (blockIdx.x * (blockDim.x >> 5) + warp) * 32;
    if (base >= E) return;
    const int cnt = min(32, E - base);

    float4 vmax = make_float4(0.f, 0.f, 0.f, 0.f);
    int cur = -1;

    if (cnt == 32) {
        uint2 praw[PF];
#pragma unroll
        for (int i = 0; i < PF; i++) {
            int n = __ldg(nb + base + i);
            praw[i] = __ldg(P2 + (size_t)n * 32 + lane);
        }
#pragma unroll
        for (int i = 0; i < 32; i++) {
            int e = base + i;
            int s = __ldg(seg + e);
            float4 a = __ldg(ai + e);
            uint2 raw = praw[i & (PF - 1)];
            float2 p01 = __bfloat1622float2(*reinterpret_cast<__nv_bfloat162*>(&raw.x));
            float2 p23 = __bfloat1622float2(*reinterpret_cast<__nv_bfloat162*>(&raw.y));

            float4 h;
            h.x = fmaxf(fmaf(a.x, w0.x, fmaf(a.y, w1.x, fmaf(a.z, w2.x, fmaf(a.w, w3.x, p01.x)))), 0.f);
            h.y = fmaxf(fmaf(a.x, w0.y, fmaf(a.y, w1.y, fmaf(a.z, w2.y, fmaf(a.w, w3.y, p01.y)))), 0.f);
            h.z = fmaxf(fmaf(a.x, w0.z, fmaf(a.y, w1.z, fmaf(a.z, w2.z, fmaf(a.w, w3.z, p23.x)))), 0.f);
            h.w = fmaxf(fmaf(a.x, w0.w, fmaf(a.y, w1.w, fmaf(a.z, w2.w, fmaf(a.w, w3.w, p23.y)))), 0.f);

            if (s != cur) {             // warp-uniform branch
                flush_max(pooled, cur, lane, vmax);
                cur = s;
                vmax = h;
            } else {
                vmax.x = fmaxf(vmax.x, h.x);
                vmax.y = fmaxf(vmax.y, h.y);
                vmax.z = fmaxf(vmax.z, h.z);
                vmax.w = fmaxf(vmax.w, h.w);
            }
            if (i + PF < 32) {
                int n = __ldg(nb + base + i + PF);
                praw[i & (PF - 1)] = __ldg(P2 + (size_t)n * 32 + lane);
            }
        }
    } else {
        for (int i = 0; i < cnt; i++) {
            int e = base + i;
            int s = __ldg(seg + e);
            int n = __ldg(nb + e);
            float4 a = __ldg(ai + e);
            uint2 raw = __ldg(P2 + (size_t)n * 32 + lane);
            float2 p01 = __bfloat1622float2(*reinterpret_cast<__nv_bfloat162*>(&raw.x));
            float2 p23 = __bfloat1622float2(*reinterpret_cast<__nv_bfloat162*>(&raw.y));
            float4 h;
            h.x = fmaxf(fmaf(a.x, w0.x, fmaf(a.y, w1.x, fmaf(a.z, w2.x, fmaf(a.w, w3.x, p01.x)))), 0.f);
            h.y = fmaxf(fmaf(a.x, w0.y, fmaf(a.y, w1.y, fmaf(a.z, w2.y, fmaf(a.w, w3.y, p01.y)))), 0.f);
            h.z = fmaxf(fmaf(a.x, w0.z, fmaf(a.y, w1.z, fmaf(a.z, w2.z, fmaf(a.w, w3.z, p23.x)))), 0.f);
            h.w = fmaxf(fmaf(a.x, w0.w, fmaf(a.y, w1.w, fmaf(a.z, w2.w, fmaf(a.w, w3.w, p23.y)))), 0.f);
            if (s != cur) {
                flush_max(pooled, cur, lane, vmax);
                cur = s; vmax = h;
            } else {
                vmax.x = fmaxf(vmax.x, h.x); vmax.y = fmaxf(vmax.y, h.y);
                vmax.z = fmaxf(vmax.z, h.z); vmax.w = fmaxf(vmax.w, h.w);
            }
        }
    }
    flush_max(pooled, cur, lane, vmax);
}

// ---------------------------------------------------------------------------
extern "C" void kernel_launch(void* const* d_in, const int* in_sizes, int n_in,
                              void* d_out, int out_size) {
    const float* interpolated = (const float*)d_in[0];
    const float* add_info     = (const float*)d_in[1];
    const int*   nb           = (const int*)d_in[2];
    const int*   seg          = (const int*)d_in[3];
    const float* Wb0 = (const float*)d_in[4];
    const float* bb0 = (const float*)d_in[5];
    const float* Wo0 = (const float*)d_in[6];
    const float* bo0 = (const float*)d_in[7];
    const float* Wb1 = (const float*)d_in[8];
    const float* bb1 = (const float*)d_in[9];
    const float* Wo1 = (const float*)d_in[10];
    const float* bo1 = (const float*)d_in[11];
    const float* Wf  = (const float*)d_in[12];
    const float* bf  = (const float*)d_in[13];

    const int N = in_sizes[0] / 128;
    const int E = in_sizes[2];

    __nv_bfloat16* Pb;
    float *pooled, *x1;
    cudaGetSymbolAddress((void**)&Pb,     g_Pb);
    cudaGetSymbolAddress((void**)&pooled, g_pooled);
    cudaGetSymbolAddress((void**)&x1,     g_x1);

    const int gemmGrid = (N + 127) / 128;
    const int edgeGrid = (E + 255) / 256;     // 8 warps/CTA x 32 edges/warp
    const size_t poolBytes = (size_t)N * 128 * sizeof(float);
    const float4* ai = (const float4*)add_info;
    const uint2*  P2 = (const uint2*)Pb;

    // ---- Block 0 ----
    cudaMemsetAsync(pooled, 0, poolBytes);
    gemm_kernel<false, true, false><<<gemmGrid, 256>>>(
        interpolated, Wb0, bb0, nullptr, nullptr, Pb, nullptr, nullptr, nullptr, N);
    edge_kernel<<<edgeGrid, 256>>>(P2, ai, nb, seg, Wb0 + 128 * 128, pooled, E);
    gemm_kernel<true, false, false><<<gemmGrid, 256>>>(
        pooled, Wo0, bo0, interpolated, x1, nullptr, nullptr, nullptr, nullptr, N);

    // ---- Block 1 ----
    cudaMemsetAsync(pooled, 0, poolBytes);
    gemm_kernel<false, true, false><<<gemmGrid, 256>>>(
        x1, Wb1, bb1, nullptr, nullptr, Pb, nullptr, nullptr, nullptr, N);
    edge_kernel<<<edgeGrid, 256>>>(P2, ai, nb, seg, Wb1 + 128 * 128, pooled, E);
    // Final GEMM fused with output projection: out = (x1 + pooled@Wo1 + bo1) @ Wf + bf
    gemm_kernel<true, false, true><<<gemmGrid, 256>>>(
        pooled, Wo1, bo1, x1, nullptr, nullptr, Wf, bf, (float*)d_out, N);
}

// round 5
// speedup vs baseline: 1.8655x; 1.0137x over previous
#include <cuda_runtime.h>
#include <cuda_bf16.h>
#include <mma.h>

using namespace nvcuda;

constexpr int DMAX = 128;
constexpr int NMAX = 50000;

__device__ __nv_bfloat16 g_Pb[(size_t)NMAX * DMAX];   // P in bf16 (halves gather traffic)
__device__ float g_pooled[(size_t)NMAX * DMAX];
__device__ float g_x1[(size_t)NMAX * DMAX];
// Pre-split weight matrices: [0]=Wb0(128 top rows) [1]=Wo0 [2]=Wb1 [3]=Wo1
__device__ __nv_bfloat16 g_Wh[4 * 128 * 128];
__device__ __nv_bfloat16 g_Wl[4 * 128 * 128];

__device__ __forceinline__ void split_bf16(float v, __nv_bfloat16& h, __nv_bfloat16& l) {
    h = __float2bfloat16(v);
    l = __float2bfloat16(v - __bfloat162float(h));
}

// ---------------------------------------------------------------------------
// Prep: split 4 weight matrices (128x128 each) into bf16 hi/lo. One float4 per
// thread, 16384 float4 total.
// ---------------------------------------------------------------------------
__global__ void split_w_kernel(const float* __restrict__ W0, const float* __restrict__ W1,
                               const float* __restrict__ W2, const float* __restrict__ W3,
                               __nv_bfloat16* __restrict__ Wh, __nv_bfloat16* __restrict__ Wl) {
    int idx = blockIdx.x * blockDim.x + threadIdx.x;   // float4 index, 0..16383
    if (idx >= 4 * 4096) return;
    int m = idx >> 12;                                  // matrix 0..3
    int off = idx & 4095;                               // float4 within matrix
    const float* W = (m == 0) ? W0 : (m == 1) ? W1 : (m == 2) ? W2 : W3;
    float4 v = reinterpret_cast<const float4*>(W)[off];
    __nv_bfloat16 h[4], l[4];
    split_bf16(v.x, h[0], l[0]); split_bf16(v.y, h[1], l[1]);
    split_bf16(v.z, h[2], l[2]); split_bf16(v.w, h[3], l[3]);
    reinterpret_cast<uint2*>(Wh)[idx] = *reinterpret_cast<uint2*>(h);
    reinterpret_cast<uint2*>(Wl)[idx] = *reinterpret_cast<uint2*>(l);
}

// ---------------------------------------------------------------------------
// bf16 tensor-core GEMM, 3-term split (Ah*Wh + Al*Wh + Ah*Wl), fp32 accum.
// A: Nrows x 128 fp32 (split in-kernel). W: pre-split bf16 hi/lo 128x128.
// CTA tile 128x128, 8 warps (2M x 4N), warp tile 64x32. k-chunk 32.
// ---------------------------------------------------------------------------
constexpr int KC   = 32;
constexpr int LDAB = 40;    // bf16: 32 + 8 pad
constexpr int LDBB = 136;   // bf16: 128 + 8 pad (mult of 8 -> uint4 aligned)
constexpr int LDC  = 132;
constexpr int SM_AH = 0;
constexpr int SM_AL = SM_AH + 128 * LDAB;  // 5120
constexpr int SM_BH = SM_AL + 128 * LDAB;  // 10240
constexpr int SM_BL = SM_BH + KC * LDBB;   // 14592
constexpr int SMEM_BF16 = SM_BL + KC * LDBB;   // 18944 bf16 = 37,888 B
static_assert(SMEM_BF16 * 2 >= 64 * LDC * 4, "C stage fits");

template <bool RES, bool OUT_BF16, bool FINAL>
__global__ __launch_bounds__(256, 2) void gemm_kernel(
        const float* __restrict__ A,
        const __nv_bfloat16* __restrict__ Wh, const __nv_bfloat16* __restrict__ Wl,
        const float* __restrict__ bias, const float* __restrict__ R,
        float* __restrict__ Cf, __nv_bfloat16* __restrict__ Cb,
        const float* __restrict__ Wf, const float* __restrict__ bf,
        float* __restrict__ out, int Nrows) {
    __shared__ __align__(16) char smem_raw[SMEM_BF16 * 2];
    __nv_bfloat16* sb = reinterpret_cast<__nv_bfloat16*>(smem_raw);
    __nv_bfloat16* sAh = sb + SM_AH;
    __nv_bfloat16* sAl = sb + SM_AL;
    __nv_bfloat16* sBh = sb + SM_BH;
    __nv_bfloat16* sBl = sb + SM_BL;
    float* sC = reinterpret_cast<float*>(smem_raw);

    const int tid  = threadIdx.x;
    const int lane = tid & 31;
    const int warp = tid >> 5;
    const int wm = warp >> 2;     // 0..1 : rows [wm*64, +64)
    const int wn = warp & 3;      // 0..3 : cols [wn*32, +32)
    const int row0 = blockIdx.x * 128;

    float4 wfv = make_float4(0.f, 0.f, 0.f, 0.f);
    float bf0 = 0.f;
    if (FINAL) { wfv = reinterpret_cast<const float4*>(Wf)[lane]; bf0 = bf[0]; }

    wmma::fragment<wmma::accumulator, 16, 16, 16, float> acc[4][2];
#pragma unroll
    for (int i = 0; i < 4; i++)
#pragma unroll
        for (int j = 0; j < 2; j++) wmma::fill_fragment(acc[i][j], 0.0f);

#pragma unroll 1
    for (int k0 = 0; k0 < 128; k0 += KC) {
        // A chunk: 128 x 32 fp32 = 1024 float4, 4/thread -> split to bf16 hi/lo
#pragma unroll
        for (int it = 0; it < 4; it++) {
            int idx = tid + it * 256;
            int r = idx >> 3;          // 0..127
            int c4 = idx & 7;          // float4 col within 32
            float4 v = make_float4(0.f, 0.f, 0.f, 0.f);
            if (row0 + r < Nrows)
                v = reinterpret_cast<const float4*>(A + (size_t)(row0 + r) * 128 + k0)[c4];
            __nv_bfloat16 h[4], l[4];
            split_bf16(v.x, h[0], l[0]); split_bf16(v.y, h[1], l[1]);
            split_bf16(v.z, h[2], l[2]); split_bf16(v.w, h[3], l[3]);
            *reinterpret_cast<uint2*>(sAh + r * LDAB + c4 * 4) = *reinterpret_cast<uint2*>(h);
            *reinterpret_cast<uint2*>(sAl + r * LDAB + c4 * 4) = *reinterpret_cast<uint2*>(l);
        }
        // W chunk: 32 rows x 128 bf16, hi+lo = 1024 uint4 total, 4/thread, no ALU
#pragma unroll
        for (int it = 0; it < 2; it++) {
            int idx = tid + it * 256;          // 0..511 (uint4 index into 32x128)
            int r = idx >> 4;                  // 0..31
            int c8 = idx & 15;                 // uint4 col (8 bf16 each)
            const uint4* srcH = reinterpret_cast<const uint4*>(Wh + (size_t)(k0 + r) * 128) + c8;
            const uint4* srcL = reinterpret_cast<const uint4*>(Wl + (size_t)(k0 + r) * 128) + c8;
            *reinterpret_cast<uint4*>(sBh + r * LDBB + c8 * 8) = __ldg(srcH);
            *reinterpret_cast<uint4*>(sBl + r * LDBB + c8 * 8) = __ldg(srcL);
        }
        __syncthreads();

#pragma unroll
        for (int ks = 0; ks < 2; ks++) {
            const int koff = ks * 16;
            wmma::fragment<wmma::matrix_b, 16, 16, 16, __nv_bfloat16, wmma::row_major> bh[2], bl[2];
#pragma unroll
            for (int j = 0; j < 2; j++) {
                wmma::load_matrix_sync(bh[j], sBh + koff * LDBB + wn * 32 + j * 16, LDBB);
                wmma::load_matrix_sync(bl[j], sBl + koff * LDBB + wn * 32 + j * 16, LDBB);
            }
#pragma unroll
            for (int i = 0; i < 4; i++) {
                wmma::fragment<wmma::matrix_a, 16, 16, 16, __nv_bfloat16, wmma::row_major> ah, al;
                wmma::load_matrix_sync(ah, sAh + (wm * 64 + i * 16) * LDAB + koff, LDAB);
                wmma::load_matrix_sync(al, sAl + (wm * 64 + i * 16) * LDAB + koff, LDAB);
#pragma unroll
                for (int j = 0; j < 2; j++) {
                    wmma::mma_sync(acc[i][j], ah, bh[j], acc[i][j]);
                    wmma::mma_sync(acc[i][j], al, bh[j], acc[i][j]);
                    wmma::mma_sync(acc[i][j], ah, bl[j], acc[i][j]);
                }
            }
        }
        __syncthreads();
    }

    // Epilogue in two 64-row halves, staged through smem.
#pragma unroll
    for (int half = 0; half < 2; half++) {
        __syncthreads();
        if (wm == half) {
#pragma unroll
            for (int i = 0; i < 4; i++)
#pragma unroll
                for (int j = 0; j < 2; j++)
                    wmma::store_matrix_sync(sC + (i * 16) * LDC + wn * 32 + j * 16,
                                            acc[i][j], LDC, wmma::mem_row_major);
        }
        __syncthreads();
#pragma unroll
        for (int it = 0; it < 8; it++) {
            int idx = tid + it * 256;
            int r = idx >> 5;            // 0..63
            int c4 = idx & 31;           // == lane
            int grow = row0 + half * 64 + r;
            if (grow < Nrows) {
                float4 o = *reinterpret_cast<float4*>(sC + r * LDC + c4 * 4);
                float4 bv = reinterpret_cast<const float4*>(bias)[c4];
                o.x += bv.x; o.y += bv.y; o.z += bv.z; o.w += bv.w;
                if (RES) {
                    float4 rv = reinterpret_cast<const float4*>(R + (size_t)grow * 128)[c4];
                    o.x += rv.x; o.y += rv.y; o.z += rv.z; o.w += rv.w;
                }
                if (FINAL) {
                    float s = o.x * wfv.x + o.y * wfv.y + o.z * wfv.z + o.w * wfv.w;
#pragma unroll
                    for (int off = 16; off; off >>= 1)
                        s += __shfl_xor_sync(0xFFFFFFFFu, s, off);
                    if (lane == 0) out[grow] = s + bf0;
                } else if (OUT_BF16) {
                    __nv_bfloat16 b4[4];
                    b4[0] = __float2bfloat16(o.x); b4[1] = __float2bfloat16(o.y);
                    b4[2] = __float2bfloat16(o.z); b4[3] = __float2bfloat16(o.w);
                    reinterpret_cast<uint2*>(Cb + (size_t)grow * 128)[c4] =
                        *reinterpret_cast<uint2*>(b4);
                } else {
                    reinterpret_cast<float4*>(Cf + (size_t)grow * 128)[c4] = o;
                }
            }
        }
    }
}

// ---------------------------------------------------------------------------
// Edge kernel. vmax >= 0 invariant => max(vmax, h) == max(vmax, relu(h)), so
// relu is applied only at segment start. atomicMax on int bits valid for
// nonnegative floats; pooled init 0.
// ---------------------------------------------------------------------------
__device__ __forceinline__ void flush_max(float* pooled, int seg, int lane, float4 v) {
    if (seg < 0) return;
    int* p = reinterpret_cast<int*>(pooled + (size_t)seg * 128 + lane * 4);
    if (v.x > 0.f) atomicMax(p + 0, __float_as_int(v.x));
    if (v.y > 0.f) atomicMax(p + 1, __float_as_int(v.y));
    if (v.z > 0.f) atomicMax(p + 2, __float_as_int(v.z));
    if (v.w > 0.f) atomicMax(p + 3, __float_as_int(v.w));
}

constexpr int PF = 8;

__global__ __launch_bounds__(256) void edge_kernel(
        const uint2* __restrict__ P2,      // N x 32 uint2 (bf16 rows, 256B)
        const float4* __restrict__ ai,
        const int* __restrict__ nb, const int* __restrict__ seg,
        const float* __restrict__ Wba, float* __restrict__ pooled, int E) {
    __shared__ float4 wsh[128];
    const int tid = threadIdx.x;
    if (tid < 128) wsh[tid] = reinterpret_cast<const float4*>(Wba)[tid];
    __syncthreads();

    const int lane = tid & 31;
    const int warp = tid >> 5;
    const float4 w0 = wsh[lane];
    const float4 w1 = wsh[32 + lane];
    const float4 w2 = wsh[64 + lane];
    const float4 w3 = wsh[96 + lane];

    const int base = (blockIdx.x * (blockDim.x >> 5) + warp) * 32;
    if (base >= E) return;
    const int cnt = min(32, E - base);

    float4 vmax = make_float4(0.f, 0.f, 0.f, 0.f);
    int cur = -1;

    if (cnt == 32) {
        uint2 praw[PF];
#pragma unroll
        for (int i = 0; i < PF; i++) {
            int n = __ldg(nb + base + i);
            praw[i] = __ldg(P2 + (size_t)n * 32 + lane);
        }
#pragma unroll
        for (int i = 0; i < 32; i++) {
            int e = base + i;
            int s = __ldg(seg + e);
            float4 a = __ldg(ai + e);
            uint2 raw = praw[i & (PF - 1)];
            float2 p01 = __bfloat1622float2(*reinterpret_cast<__nv_bfloat162*>(&raw.x));
            float2 p23 = __bfloat1622float2(*reinterpret_cast<__nv_bfloat162*>(&raw.y));

            float4 h;    // pre-relu
            h.x = fmaf(a.x, w0.x, fmaf(a.y, w1.x, fmaf(a.z, w2.x, fmaf(a.w, w3.x, p01.x))));
            h.y = fmaf(a.x, w0.y, fmaf(a.y, w1.y, fmaf(a.z, w2.y, fmaf(a.w, w3.y, p01.y))));
            h.z = fmaf(a.x, w0.z, fmaf(a.y, w1.z, fmaf(a.z, w2.z, fmaf(a.w, w3.z, p23.x))));
            h.w = fmaf(a.x, w0.w, fmaf(a.y, w1.w, fmaf(a.z, w2.w, fmaf(a.w, w3.w, p23.y))));

            if (s != cur) {             // warp-uniform branch
                flush_max(pooled, cur, lane, vmax);
                cur = s;
                vmax.x = fmaxf(h.x, 0.f); vmax.y = fmaxf(h.y, 0.f);
                vmax.z = fmaxf(h.z, 0.f); vmax.w = fmaxf(h.w, 0.f);
            } else {                    // vmax >= 0, relu folded into max
                vmax.x = fmaxf(vmax.x, h.x);
                vmax.y = fmaxf(vmax.y, h.y);
                vmax.z = fmaxf(vmax.z, h.z);
                vmax.w = fmaxf(vmax.w, h.w);
            }
            if (i + PF < 32) {
                int n = __ldg(nb + base + i + PF);
                praw[i & (PF - 1)] = __ldg(P2 + (size_t)n * 32 + lane);
            }
        }
    } else {
        for (int i = 0; i < cnt; i++) {
            int e = base + i;
            int s = __ldg(seg + e);
            int n = __ldg(nb + e);
            float4 a = __ldg(ai + e);
            uint2 raw = __ldg(P2 + (size_t)n * 32 + lane);
            float2 p01 = __bfloat1622float2(*reinterpret_cast<__nv_bfloat162*>(&raw.x));
            float2 p23 = __bfloat1622float2(*reinterpret_cast<__nv_bfloat162*>(&raw.y));
            float4 h;
            h.x = fmaf(a.x, w0.x, fmaf(a.y, w1.x, fmaf(a.z, w2.x, fmaf(a.w, w3.x, p01.x))));
            h.y = fmaf(a.x, w0.y, fmaf(a.y, w1.y, fmaf(a.z, w2.y, fmaf(a.w, w3.y, p01.y))));
            h.z = fmaf(a.x, w0.z, fmaf(a.y, w1.z, fmaf(a.z, w2.z, fmaf(a.w, w3.z, p23.x))));
            h.w = fmaf(a.x, w0.w, fmaf(a.y, w1.w, fmaf(a.z, w2.w, fmaf(a.w, w3.w, p23.y))));
            if (s != cur) {
                flush_max(pooled, cur, lane, vmax);
                cur = s;
                vmax.x = fmaxf(h.x, 0.f); vmax.y = fmaxf(h.y, 0.f);
                vmax.z = fmaxf(h.z, 0.f); vmax.w = fmaxf(h.w, 0.f);
            } else {
                vmax.x = fmaxf(vmax.x, h.x); vmax.y = fmaxf(vmax.y, h.y);
                vmax.z = fmaxf(vmax.z, h.z); vmax.w = fmaxf(vmax.w, h.w);
            }
        }
    }
    flush_max(pooled, cur, lane, vmax);
}

// ---------------------------------------------------------------------------
extern "C" void kernel_launch(void* const* d_in, const int* in_sizes, int n_in,
                              void* d_out, int out_size) {
    const float* interpolated = (const float*)d_in[0];
    const float* add_info     = (const float*)d_in[1];
    const int*   nb           = (const int*)d_in[2];
    const int*   seg          = (const int*)d_in[3];
    const float* Wb0 = (const float*)d_in[4];
    const float* bb0 = (const float*)d_in[5];
    const float* Wo0 = (const float*)d_in[6];
    const float* bo0 = (const float*)d_in[7];
    const float* Wb1 = (const float*)d_in[8];
    const float* bb1 = (const float*)d_in[9];
    const float* Wo1 = (const float*)d_in[10];
    const float* bo1 = (const float*)d_in[11];
    const float* Wf  = (const float*)d_in[12];
    const float* bf  = (const float*)d_in[13];

    const int N = in_sizes[0] / 128;
    const int E = in_sizes[2];

    __nv_bfloat16 *Pb, *Wh, *Wl;
    float *pooled, *x1;
    cudaGetSymbolAddress((void**)&Pb,     g_Pb);
    cudaGetSymbolAddress((void**)&pooled, g_pooled);
    cudaGetSymbolAddress((void**)&x1,     g_x1);
    cudaGetSymbolAddress((void**)&Wh,     g_Wh);
    cudaGetSymbolAddress((void**)&Wl,     g_Wl);

    const int gemmGrid = (N + 127) / 128;
    const int edgeGrid = (E + 255) / 256;     // 8 warps/CTA x 32 edges/warp
    const size_t poolBytes = (size_t)N * 128 * sizeof(float);
    const float4* ai = (const float4*)add_info;
    const uint2*  P2 = (const uint2*)Pb;
    const int WM = 128 * 128;   // per-matrix bf16 elements

    // Pre-split the four 128x128 weight matrices (once per launch).
    split_w_kernel<<<64, 256>>>(Wb0, Wo0, Wb1, Wo1, Wh, Wl);
    cudaMemsetAsync(pooled, 0, poolBytes);

    // ---- Block 0 ----
    gemm_kernel<false, true, false><<<gemmGrid, 256>>>(
        interpolated, Wh + 0 * WM, Wl + 0 * WM, bb0, nullptr,
        nullptr, Pb, nullptr, nullptr, nullptr, N);
    edge_kernel<<<edgeGrid, 256>>>(P2, ai, nb, seg, Wb0 + 128 * 128, pooled, E);
    gemm_kernel<true, false, false><<<gemmGrid, 256>>>(
        pooled, Wh + 1 * WM, Wl + 1 * WM, bo0, interpolated,
        x1, nullptr, nullptr, nullptr, nullptr, N);

    // ---- Block 1 ----
    cudaMemsetAsync(pooled, 0, poolBytes);
    gemm_kernel<false, true, false><<<gemmGrid, 256>>>(
        x1, Wh + 2 * WM, Wl + 2 * WM, bb1, nullptr,
        nullptr, Pb, nullptr, nullptr, nullptr, N);
    edge_kernel<<<edgeGrid, 256>>>(P2, ai, nb, seg, Wb1 + 128 * 128, pooled, E);
    // Final GEMM fused with output projection: out = (x1 + pooled@Wo1 + bo1) @ Wf + bf
    gemm_kernel<true, false, true><<<gemmGrid, 256>>>(
        pooled, Wh + 3 * WM, Wl + 3 * WM, bo1, x1,
        nullptr, nullptr, Wf, bf, (float*)d_out, N);
}

// round 9
// speedup vs baseline: 2.0465x; 1.0970x over previous
#include <cuda_runtime.h>
#include <cuda_bf16.h>
#include <mma.h>

using namespace nvcuda;

constexpr int DMAX = 128;
constexpr int NMAX = 50000;

__device__ __nv_bfloat16 g_Pb[(size_t)NMAX * DMAX];
__device__ float g_pool0[(size_t)NMAX * DMAX];
__device__ float g_pool1[(size_t)NMAX * DMAX];
// Pre-split bf16 hi/lo weights: slot 0 = Wb0(top), 1 = Wb1(top), 2 = Wc10
__device__ __nv_bfloat16 g_Wh[3 * 128 * 128];
__device__ __nv_bfloat16 g_Wl[3 * 128 * 128];
__device__ float g_Wc10[128 * 128];   // Wo0 @ Wb1top (fp32)
__device__ float g_wf0[128];          // Wo0 @ Wf
__device__ float g_wf1[128];          // Wo1 @ Wf
__device__ float g_c1[128];           // bo0 @ Wb1top + bb1
__device__ float g_cf[1];             // bo0@Wf... no: (bo0@Wf)+(bo1@Wf)+bf? see prep

__device__ __forceinline__ void split_bf16(float v, __nv_bfloat16& h, __nv_bfloat16& l) {
    h = __float2bfloat16(v);
    l = __float2bfloat16(v - __bfloat162float(h));
}

// ---------------------------------------------------------------------------
// prepA: tiny combined-weight precompute (fp32).
//   Wc10 = Wo0 @ Wb1top ; wf0 = Wo0@Wf ; wf1 = Wo1@Wf ;
//   c1 = bo0@Wb1top + bb1 ; cf = bo0@Wf + bo1@Wf + bf
// out = x2@Wf+bf = interp@Wf + pooled0@wf0 + pooled1@wf1 + cf
// P1  = interp@Wb1top + pooled0@Wc10 + c1
// ---------------------------------------------------------------------------
__global__ void prepA_kernel(const float* __restrict__ Wo0, const float* __restrict__ Wb1,
                             const float* __restrict__ Wo1, const float* __restrict__ Wf,
                             const float* __restrict__ bb1, const float* __restrict__ bo0,
                             const float* __restrict__ bo1, const float* __restrict__ bf,
                             float* __restrict__ Wc10, float* __restrict__ wf0,
                             float* __restrict__ wf1, float* __restrict__ c1,
                             float* __restrict__ cf) {
    int g = blockIdx.x, tid = threadIdx.x;
    if (g < 64) {                       // Wc10: 16384 outputs
        int idx = g * 256 + tid;
        int i = idx >> 7, j = idx & 127;
        float s = 0.f;
        for (int k = 0; k < 128; k++) s = fmaf(Wo0[i * 128 + k], Wb1[k * 128 + j], s);
        Wc10[idx] = s;
    } else if (g == 64) {
        if (tid < 128) {
            float s = 0.f;
            for (int k = 0; k < 128; k++) s = fmaf(Wo0[tid * 128 + k], Wf[k], s);
            wf0[tid] = s;
        } else {
            int r = tid - 128;
            float s = 0.f;
            for (int k = 0; k < 128; k++) s = fmaf(Wo1[r * 128 + k], Wf[k], s);
            wf1[r] = s;
        }
    } else {
        if (tid < 128) {
            float s = 0.f;
            for (int k = 0; k < 128; k++) s = fmaf(bo0[k], Wb1[k * 128 + tid], s);
            c1[tid] = s + bb1[tid];
        } else if (tid == 128) {
            float s = 0.f;
            for (int k = 0; k < 128; k++) s = fmaf(bo0[k] + bo1[k], Wf[k], s);
            cf[0] = s + bf[0];
        }
    }
}

// prepB: split 3 matrices (top 128x128 each) into bf16 hi/lo.
__global__ void split_w_kernel(const float* __restrict__ W0, const float* __restrict__ W1,
                               const float* __restrict__ W2,
                               __nv_bfloat16* __restrict__ Wh, __nv_bfloat16* __restrict__ Wl) {
    int idx = blockIdx.x * blockDim.x + threadIdx.x;   // float4 idx, 0..12287
    if (idx >= 3 * 4096) return;
    int m = idx >> 12;
    int off = idx & 4095;
    const float* W = (m == 0) ? W0 : (m == 1) ? W1 : W2;
    float4 v = reinterpret_cast<const float4*>(W)[off];
    __nv_bfloat16 h[4], l[4];
    split_bf16(v.x, h[0], l[0]); split_bf16(v.y, h[1], l[1]);
    split_bf16(v.z, h[2], l[2]); split_bf16(v.w, h[3], l[3]);
    reinterpret_cast<uint2*>(Wh)[idx] = *reinterpret_cast<uint2*>(h);
    reinterpret_cast<uint2*>(Wl)[idx] = *reinterpret_cast<uint2*>(l);
}

// ---------------------------------------------------------------------------
// bf16 tensor-core GEMM, split accumulation, optional dual-A:
//   acc = A1@W1 (3-term: Ah*Wh + Al*Wh + Ah*Wl)
//       [+ A2@W2 (2-term: Ah*Wh + Ah*Wl, A2 rounded to bf16)]   (DUAL)
//   C = acc + bias; out as bf16 (Cb) or fp32 (Cf).
// CTA tile 128x128, 8 warps (2M x 4N), warp tile 64x32, k-chunk 32.
// ---------------------------------------------------------------------------
constexpr int KC   = 32;
constexpr int LDAB = 40;
constexpr int LDBB = 136;
constexpr int LDC  = 132;
constexpr int SM_AH = 0;
constexpr int SM_AL = SM_AH + 128 * LDAB;
constexpr int SM_BH = SM_AL + 128 * LDAB;
constexpr int SM_BL = SM_BH + KC * LDBB;
constexpr int SMEM_BF16 = SM_BL + KC * LDBB;   // 18944 bf16 = 37,888 B
static_assert(SMEM_BF16 * 2 >= 64 * LDC * 4, "C stage fits");

template <bool OUT_BF16, bool DUAL>
__global__ __launch_bounds__(256, 2) void gemm_kernel(
        const float* __restrict__ A1,
        const __nv_bfloat16* __restrict__ Wh1, const __nv_bfloat16* __restrict__ Wl1,
        const float* __restrict__ A2,
        const __nv_bfloat16* __restrict__ Wh2, const __nv_bfloat16* __restrict__ Wl2,
        const float* __restrict__ bias,
        float* __restrict__ Cf, __nv_bfloat16* __restrict__ Cb, int Nrows) {
    __shared__ __align__(16) char smem_raw[SMEM_BF16 * 2];
    __nv_bfloat16* sb = reinterpret_cast<__nv_bfloat16*>(smem_raw);
    __nv_bfloat16* sAh = sb + SM_AH;
    __nv_bfloat16* sAl = sb + SM_AL;
    __nv_bfloat16* sBh = sb + SM_BH;
    __nv_bfloat16* sBl = sb + SM_BL;
    float* sC = reinterpret_cast<float*>(smem_raw);

    const int tid  = threadIdx.x;
    const int lane = tid & 31;
    const int warp = tid >> 5;
    const int wm = warp >> 2;
    const int wn = warp & 3;
    const int row0 = blockIdx.x * 128;

    wmma::fragment<wmma::accumulator, 16, 16, 16, float> acc[4][2];
#pragma unroll
    for (int i = 0; i < 4; i++)
#pragma unroll
        for (int j = 0; j < 2; j++) wmma::fill_fragment(acc[i][j], 0.0f);

    const int nPhase = DUAL ? 2 : 1;
#pragma unroll 1
    for (int ph = 0; ph < nPhase; ph++) {
        const float* A = (ph == 0) ? A1 : A2;
        const __nv_bfloat16* WhP = (ph == 0) ? Wh1 : Wh2;
        const __nv_bfloat16* WlP = (ph == 0) ? Wl1 : Wl2;
        const bool doSplit = (ph == 0);   // phase 2: A rounded to bf16, 2-term

#pragma unroll 1
        for (int k0 = 0; k0 < 128; k0 += KC) {
            // A chunk: 128 x 32 fp32 = 1024 float4, 4/thread
#pragma unroll
            for (int it = 0; it < 4; it++) {
                int idx = tid + it * 256;
                int r = idx >> 3;
                int c4 = idx & 7;
                float4 v = make_float4(0.f, 0.f, 0.f, 0.f);
                if (row0 + r < Nrows)
                    v = reinterpret_cast<const float4*>(A + (size_t)(row0 + r) * 128 + k0)[c4];
                __nv_bfloat16 h[4], l[4];
                split_bf16(v.x, h[0], l[0]); split_bf16(v.y, h[1], l[1]);
                split_bf16(v.z, h[2], l[2]); split_bf16(v.w, h[3], l[3]);
                *reinterpret_cast<uint2*>(sAh + r * LDAB + c4 * 4) = *reinterpret_cast<uint2*>(h);
                if (doSplit)
                    *reinterpret_cast<uint2*>(sAl + r * LDAB + c4 * 4) = *reinterpret_cast<uint2*>(l);
            }
            // W chunk: 32 x 128 bf16 hi+lo, raw copies
#pragma unroll
            for (int it = 0; it < 2; it++) {
                int idx = tid + it * 256;
                int r = idx >> 4;
                int c8 = idx & 15;
                const uint4* srcH = reinterpret_cast<const uint4*>(WhP + (size_t)(k0 + r) * 128) + c8;
                const uint4* srcL = reinterpret_cast<const uint4*>(WlP + (size_t)(k0 + r) * 128) + c8;
                *reinterpret_cast<uint4*>(sBh + r * LDBB + c8 * 8) = __ldg(srcH);
                *reinterpret_cast<uint4*>(sBl + r * LDBB + c8 * 8) = __ldg(srcL);
            }
            __syncthreads();

#pragma unroll
            for (int ks = 0; ks < 2; ks++) {
                const int koff = ks * 16;
                wmma::fragment<wmma::matrix_b, 16, 16, 16, __nv_bfloat16, wmma::row_major> bh[2], bl[2];
#pragma unroll
                for (int j = 0; j < 2; j++) {
                    wmma::load_matrix_sync(bh[j], sBh + koff * LDBB + wn * 32 + j * 16, LDBB);
                    wmma::load_matrix_sync(bl[j], sBl + koff * LDBB + wn * 32 + j * 16, LDBB);
                }
#pragma unroll
                for (int i = 0; i < 4; i++) {
                    wmma::fragment<wmma::matrix_a, 16, 16, 16, __nv_bfloat16, wmma::row_major> ah, al;
                    wmma::load_matrix_sync(ah, sAh + (wm * 64 + i * 16) * LDAB + koff, LDAB);
                    if (doSplit)
                        wmma::load_matrix_sync(al, sAl + (wm * 64 + i * 16) * LDAB + koff, LDAB);
#pragma unroll
                    for (int j = 0; j < 2; j++) {
                        wmma::mma_sync(acc[i][j], ah, bh[j], acc[i][j]);
                        if (doSplit) wmma::mma_sync(acc[i][j], al, bh[j], acc[i][j]);
                        wmma::mma_sync(acc[i][j], ah, bl[j], acc[i][j]);
                    }
                }
            }
            __syncthreads();
        }
    }

    // Epilogue: two 64-row halves staged through smem.
#pragma unroll
    for (int half = 0; half < 2; half++) {
        __syncthreads();
        if (wm == half) {
#pragma unroll
            for (int i = 0; i < 4; i++)
#pragma unroll
                for (int j = 0; j < 2; j++)
                    wmma::store_matrix_sync(sC + (i * 16) * LDC + wn * 32 + j * 16,
                                            acc[i][j], LDC, wmma::mem_row_major);
        }
        __syncthreads();
#pragma unroll
        for (int it = 0; it < 8; it++) {
            int idx = tid + it * 256;
            int r = idx >> 5;
            int c4 = idx & 31;
            int grow = row0 + half * 64 + r;
            if (grow < Nrows) {
                float4 o = *reinterpret_cast<float4*>(sC + r * LDC + c4 * 4);
                float4 bv = reinterpret_cast<const float4*>(bias)[c4];
                o.x += bv.x; o.y += bv.y; o.z += bv.z; o.w += bv.w;
                if (OUT_BF16) {
                    __nv_bfloat16 b4[4];
                    b4[0] = __float2bfloat16(o.x); b4[1] = __float2bfloat16(o.y);
                    b4[2] = __float2bfloat16(o.z); b4[3] = __float2bfloat16(o.w);
                    reinterpret_cast<uint2*>(Cb + (size_t)grow * 128)[c4] =
                        *reinterpret_cast<uint2*>(b4);
                } else {
                    reinterpret_cast<float4*>(Cf + (size_t)grow * 128)[c4] = o;
                }
            }
        }
    }
}

// ---------------------------------------------------------------------------
// Edge kernel (unchanged from round 5 — proven).
// ---------------------------------------------------------------------------
__device__ __forceinline__ void flush_max(float* pooled, int seg, int lane, float4 v) {
    if (seg < 0) return;
    int* p = reinterpret_cast<int*>(pooled + (size_t)seg * 128 + lane * 4);
    if (v.x > 0.f) atomicMax(p + 0, __float_as_int(v.x));
    if (v.y > 0.f) atomicMax(p + 1, __float_as_int(v.y));
    if (v.z > 0.f) atomicMax(p + 2, __float_as_int(v.z));
    if (v.w > 0.f) atomicMax(p + 3, __float_as_int(v.w));
}

constexpr int PF = 8;

__global__ __launch_bounds__(256) void edge_kernel(
        const uint2* __restrict__ P2, const float4* __restrict__ ai,
        const int* __restrict__ nb, const int* __restrict__ seg,
        const float* __restrict__ Wba, float* __restrict__ pooled, int E) {
    __shared__ float4 wsh[128];
    const int tid = threadIdx.x;
    if (tid < 128) wsh[tid] = reinterpret_cast<const float4*>(Wba)[tid];
    __syncthreads();

    const int lane = tid & 31;
    const int warp = tid >> 5;
    const float4 w0 = wsh[lane];
    const float4 w1 = wsh[32 + lane];
    const float4 w2 = wsh[64 + lane];
    const float4 w3 = wsh[96 + lane];

    const int base = (blockIdx.x * (blockDim.x >> 5) + warp) * 32;
    if (base >= E) return;
    const int cnt = min(32, E - base);

    float4 vmax = make_float4(0.f, 0.f, 0.f, 0.f);
    int cur = -1;

    if (cnt == 32) {
        uint2 praw[PF];
#pragma unroll
        for (int i = 0; i < PF; i++) {
            int n = __ldg(nb + base + i);
            praw[i] = __ldg(P2 + (size_t)n * 32 + lane);
        }
#pragma unroll
        for (int i = 0; i < 32; i++) {
            int e = base + i;
            int s = __ldg(seg + e);
            float4 a = __ldg(ai + e);
            uint2 raw = praw[i & (PF - 1)];
            float2 p01 = __bfloat1622float2(*reinterpret_cast<__nv_bfloat162*>(&raw.x));
            float2 p23 = __bfloat1622float2(*reinterpret_cast<__nv_bfloat162*>(&raw.y));

            float4 h;
            h.x = fmaf(a.x, w0.x, fmaf(a.y, w1.x, fmaf(a.z, w2.x, fmaf(a.w, w3.x, p01.x))));
            h.y = fmaf(a.x, w0.y, fmaf(a.y, w1.y, fmaf(a.z, w2.y, fmaf(a.w, w3.y, p01.y))));
            h.z = fmaf(a.x, w0.z, fmaf(a.y, w1.z, fmaf(a.z, w2.z, fmaf(a.w, w3.z, p23.x))));
            h.w = fmaf(a.x, w0.w, fmaf(a.y, w1.w, fmaf(a.z, w2.w, fmaf(a.w, w3.w, p23.y))));

            if (s != cur) {
                flush_max(pooled, cur, lane, vmax);
                cur = s;
                vmax.x = fmaxf(h.x, 0.f); vmax.y = fmaxf(h.y, 0.f);
                vmax.z = fmaxf(h.z, 0.f); vmax.w = fmaxf(h.w, 0.f);
            } else {
                vmax.x = fmaxf(vmax.x, h.x);
                vmax.y = fmaxf(vmax.y, h.y);
                vmax.z = fmaxf(vmax.z, h.z);
                vmax.w = fmaxf(vmax.w, h.w);
            }
            if (i + PF < 32) {
                int n = __ldg(nb + base + i + PF);
                praw[i & (PF - 1)] = __ldg(P2 + (size_t)n * 32 + lane);
            }
        }
    } else {
        for (int i = 0; i < cnt; i++) {
            int e = base + i;
            int s = __ldg(seg + e);
            int n = __ldg(nb + e);
            float4 a = __ldg(ai + e);
            uint2 raw = __ldg(P2 + (size_t)n * 32 + lane);
            float2 p01 = __bfloat1622float2(*reinterpret_cast<__nv_bfloat162*>(&raw.x));
            float2 p23 = __bfloat1622float2(*reinterpret_cast<__nv_bfloat162*>(&raw.y));
            float4 h;
            h.x = fmaf(a.x, w0.x, fmaf(a.y, w1.x, fmaf(a.z, w2.x, fmaf(a.w, w3.x, p01.x))));
            h.y = fmaf(a.x, w0.y, fmaf(a.y, w1.y, fmaf(a.z, w2.y, fmaf(a.w, w3.y, p01.y))));
            h.z = fmaf(a.x, w0.z, fmaf(a.y, w1.z, fmaf(a.z, w2.z, fmaf(a.w, w3.z, p23.x))));
            h.w = fmaf(a.x, w0.w, fmaf(a.y, w1.w, fmaf(a.z, w2.w, fmaf(a.w, w3.w, p23.y))));
            if (s != cur) {
                flush_max(pooled, cur, lane, vmax);
                cur = s;
                vmax.x = fmaxf(h.x, 0.f); vmax.y = fmaxf(h.y, 0.f);
                vmax.z = fmaxf(h.z, 0.f); vmax.w = fmaxf(h.w, 0.f);
            } else {
                vmax.x = fmaxf(vmax.x, h.x); vmax.y = fmaxf(vmax.y, h.y);
                vmax.z = fmaxf(vmax.z, h.z); vmax.w = fmaxf(vmax.w, h.w);
            }
        }
    }
    flush_max(pooled, cur, lane, vmax);
}

// ---------------------------------------------------------------------------
// Final: out[n] = interp[n]@Wf + pool0[n]@wf0 + pool1[n]@wf1 + cf
// ---------------------------------------------------------------------------
__global__ void final_kernel(const float* __restrict__ interp,
                             const float* __restrict__ pool0,
                             const float* __restrict__ pool1,
                             const float* __restrict__ Wf,
                             const float* __restrict__ wf0,
                             const float* __restrict__ wf1,
                             const float* __restrict__ cf,
                             float* __restrict__ out, int N) {
    int gwarp = (blockIdx.x * blockDim.x + threadIdx.x) >> 5;
    int lane = threadIdx.x & 31;
    if (gwarp >= N) return;
    float4 xv = reinterpret_cast<const float4*>(interp + (size_t)gwarp * 128)[lane];
    float4 p0 = reinterpret_cast<const float4*>(pool0 + (size_t)gwarp * 128)[lane];
    float4 p1 = reinterpret_cast<const float4*>(pool1 + (size_t)gwarp * 128)[lane];
    float4 wv = reinterpret_cast<const float4*>(Wf)[lane];
    float4 v0 = reinterpret_cast<const float4*>(wf0)[lane];
    float4 v1 = reinterpret_cast<const float4*>(wf1)[lane];
    float s = xv.x * wv.x + xv.y * wv.y + xv.z * wv.z + xv.w * wv.w
            + p0.x * v0.x + p0.y * v0.y + p0.z * v0.z + p0.w * v0.w
            + p1.x * v1.x + p1.y * v1.y + p1.z * v1.z + p1.w * v1.w;
#pragma unroll
    for (int o = 16; o; o >>= 1) s += __shfl_xor_sync(0xFFFFFFFFu, s, o);
    if (lane == 0) out[gwarp] = s + cf[0];
}

// ---------------------------------------------------------------------------
extern "C" void kernel_launch(void* const* d_in, const int* in_sizes, int n_in,
                              void* d_out, int out_size) {
    const float* interpolated = (const float*)d_in[0];
    const float* add_info     = (const float*)d_in[1];
    const int*   nb           = (const int*)d_in[2];
    const int*   seg          = (const int*)d_in[3];
    const float* Wb0 = (const float*)d_in[4];
    const float* bb0 = (const float*)d_in[5];
    const float* Wo0 = (const float*)d_in[6];
    const float* bo0 = (const float*)d_in[7];
    const float* Wb1 = (const float*)d_in[8];
    const float* bb1 = (const float*)d_in[9];
    const float* Wo1 = (const float*)d_in[10];
    const float* bo1 = (const float*)d_in[11];
    const float* Wf  = (const float*)d_in[12];
    const float* bf  = (const float*)d_in[13];

    const int N = in_sizes[0] / 128;
    const int E = in_sizes[2];

    __nv_bfloat16 *Pb, *Wh, *Wl;
    float *pool0, *pool1, *Wc10, *wf0, *wf1, *c1, *cf;
    cudaGetSymbolAddress((void**)&Pb,    g_Pb);
    cudaGetSymbolAddress((void**)&pool0, g_pool0);
    cudaGetSymbolAddress((void**)&pool1, g_pool1);
    cudaGetSymbolAddress((void**)&Wh,    g_Wh);
    cudaGetSymbolAddress((void**)&Wl,    g_Wl);
    cudaGetSymbolAddress((void**)&Wc10,  g_Wc10);
    cudaGetSymbolAddress((void**)&wf0,   g_wf0);
    cudaGetSymbolAddress((void**)&wf1,   g_wf1);
    cudaGetSymbolAddress((void**)&c1,    g_c1);
    cudaGetSymbolAddress((void**)&cf,    g_cf);

    const int gemmGrid = (N + 127) / 128;
    const int edgeGrid = (E + 255) / 256;
    const size_t poolBytes = (size_t)N * 128 * sizeof(float);
    const float4* ai = (const float4*)add_info;
    const uint2*  P2 = (const uint2*)Pb;
    const int WM = 128 * 128;

    // Prep: combined weights, then bf16 hi/lo splits (Wb0top, Wb1top, Wc10).
    prepA_kernel<<<66, 256>>>(Wo0, Wb1, Wo1, Wf, bb1, bo0, bo1, bf,
                              Wc10, wf0, wf1, c1, cf);
    split_w_kernel<<<48, 256>>>(Wb0, Wb1, Wc10, Wh, Wl);
    cudaMemsetAsync(pool0, 0, poolBytes);
    cudaMemsetAsync(pool1, 0, poolBytes);

    // Block 0: P0 = interp@Wb0top + bb0
    gemm_kernel<true, false><<<gemmGrid, 256>>>(
        interpolated, Wh + 0 * WM, Wl + 0 * WM,
        nullptr, nullptr, nullptr, bb0, nullptr, Pb, N);
    edge_kernel<<<edgeGrid, 256>>>(P2, ai, nb, seg, Wb0 + 128 * 128, pool0, E);

    // Mid (fused GEMM2+GEMM3): P1 = interp@Wb1top + pool0@Wc10 + c1
    gemm_kernel<true, true><<<gemmGrid, 256>>>(
        interpolated, Wh + 1 * WM, Wl + 1 * WM,
        pool0, Wh + 2 * WM, Wl + 2 * WM, c1, nullptr, Pb, N);
    edge_kernel<<<edgeGrid, 256>>>(P2, ai, nb, seg, Wb1 + 128 * 128, pool1, E);

    // Final (replaces GEMM4): out = interp@Wf + pool0@wf0 + pool1@wf1 + cf
    final_kernel<<<(N * 32 + 255) / 256, 256>>>(
        interpolated, pool0, pool1, Wf, wf0, wf1, cf, (float*)d_out, N);
}

// round 10
// speedup vs baseline: 2.2617x; 1.1052x over previous
#include <cuda_runtime.h>
#include <cuda_bf16.h>
#include <mma.h>

using namespace nvcuda;

constexpr int DMAX = 128;
constexpr int NMAX = 50000;
constexpr int EMAX = 1600000;

__device__ __nv_bfloat16 g_Pb[(size_t)NMAX * DMAX];
__device__ float g_pool0[(size_t)NMAX * DMAX];
__device__ float g_pool1[(size_t)NMAX * DMAX];
__device__ uint4 g_aib[EMAX];          // add_info as 4 replicated bf16x2 per edge
// Pre-split bf16 hi/lo weights: slot 0 = Wb0(top), 1 = Wb1(top), 2 = Wc10
__device__ __nv_bfloat16 g_Wh[3 * 128 * 128];
__device__ __nv_bfloat16 g_Wl[3 * 128 * 128];
__device__ float g_Wc10[128 * 128];   // Wo0 @ Wb1top (fp32)
__device__ float g_wf0[128];          // Wo0 @ Wf
__device__ float g_wf1[128];          // Wo1 @ Wf
__device__ float g_c1[128];           // bo0 @ Wb1top + bb1
__device__ float g_cf[1];             // (bo0+bo1)@Wf + bf

__device__ __forceinline__ void split_bf16(float v, __nv_bfloat16& h, __nv_bfloat16& l) {
    h = __float2bfloat16(v);
    l = __float2bfloat16(v - __bfloat162float(h));
}

// ---------------------------------------------------------------------------
// prepA: combined-weight precompute (fp32).
// ---------------------------------------------------------------------------
__global__ void prepA_kernel(const float* __restrict__ Wo0, const float* __restrict__ Wb1,
                             const float* __restrict__ Wo1, const float* __restrict__ Wf,
                             const float* __restrict__ bb1, const float* __restrict__ bo0,
                             const float* __restrict__ bo1, const float* __restrict__ bf,
                             float* __restrict__ Wc10, float* __restrict__ wf0,
                             float* __restrict__ wf1, float* __restrict__ c1,
                             float* __restrict__ cf) {
    int g = blockIdx.x, tid = threadIdx.x;
    if (g < 64) {                       // Wc10: 16384 outputs
        int idx = g * 256 + tid;
        int i = idx >> 7, j = idx & 127;
        float s = 0.f;
        for (int k = 0; k < 128; k++) s = fmaf(Wo0[i * 128 + k], Wb1[k * 128 + j], s);
        Wc10[idx] = s;
    } else if (g == 64) {
        if (tid < 128) {
            float s = 0.f;
            for (int k = 0; k < 128; k++) s = fmaf(Wo0[tid * 128 + k], Wf[k], s);
            wf0[tid] = s;
        } else {
            int r = tid - 128;
            float s = 0.f;
            for (int k = 0; k < 128; k++) s = fmaf(Wo1[r * 128 + k], Wf[k], s);
            wf1[r] = s;
        }
    } else {
        if (tid < 128) {
            float s = 0.f;
            for (int k = 0; k < 128; k++) s = fmaf(bo0[k], Wb1[k * 128 + tid], s);
            c1[tid] = s + bb1[tid];
        } else if (tid == 128) {
            float s = 0.f;
            for (int k = 0; k < 128; k++) s = fmaf(bo0[k] + bo1[k], Wf[k], s);
            cf[0] = s + bf[0];
        }
    }
}

// prepB: split 3 matrices into bf16 hi/lo.
__global__ void split_w_kernel(const float* __restrict__ W0, const float* __restrict__ W1,
                               const float* __restrict__ W2,
                               __nv_bfloat16* __restrict__ Wh, __nv_bfloat16* __restrict__ Wl) {
    int idx = blockIdx.x * blockDim.x + threadIdx.x;
    if (idx >= 3 * 4096) return;
    int m = idx >> 12;
    int off = idx & 4095;
    const float* W = (m == 0) ? W0 : (m == 1) ? W1 : W2;
    float4 v = reinterpret_cast<const float4*>(W)[off];
    __nv_bfloat16 h[4], l[4];
    split_bf16(v.x, h[0], l[0]); split_bf16(v.y, h[1], l[1]);
    split_bf16(v.z, h[2], l[2]); split_bf16(v.w, h[3], l[3]);
    reinterpret_cast<uint2*>(Wh)[idx] = *reinterpret_cast<uint2*>(h);
    reinterpret_cast<uint2*>(Wl)[idx] = *reinterpret_cast<uint2*>(l);
}

// prepC: add_info -> 4 replicated bf16x2 per edge (zero in-loop converts).
__global__ void cvt_ai_kernel(const float4* __restrict__ ai, uint4* __restrict__ aib, int E) {
    int e = blockIdx.x * blockDim.x + threadIdx.x;
    if (e >= E) return;
    float4 a = __ldg(ai + e);
    __nv_bfloat162 x = __float2bfloat162_rn(a.x);
    __nv_bfloat162 y = __float2bfloat162_rn(a.y);
    __nv_bfloat162 z = __float2bfloat162_rn(a.z);
    __nv_bfloat162 w = __float2bfloat162_rn(a.w);
    uint4 o;
    o.x = *reinterpret_cast<unsigned*>(&x);
    o.y = *reinterpret_cast<unsigned*>(&y);
    o.z = *reinterpret_cast<unsigned*>(&z);
    o.w = *reinterpret_cast<unsigned*>(&w);
    aib[e] = o;
}

// ---------------------------------------------------------------------------
// bf16 tensor-core GEMM (unchanged from round 9 — proven).
// ---------------------------------------------------------------------------
constexpr int KC   = 32;
constexpr int LDAB = 40;
constexpr int LDBB = 136;
constexpr int LDC  = 132;
constexpr int SM_AH = 0;
constexpr int SM_AL = SM_AH + 128 * LDAB;
constexpr int SM_BH = SM_AL + 128 * LDAB;
constexpr int SM_BL = SM_BH + KC * LDBB;
constexpr int SMEM_BF16 = SM_BL + KC * LDBB;
static_assert(SMEM_BF16 * 2 >= 64 * LDC * 4, "C stage fits");

template <bool OUT_BF16, bool DUAL>
__global__ __launch_bounds__(256, 2) void gemm_kernel(
        const float* __restrict__ A1,
        const __nv_bfloat16* __restrict__ Wh1, const __nv_bfloat16* __restrict__ Wl1,
        const float* __restrict__ A2,
        const __nv_bfloat16* __restrict__ Wh2, const __nv_bfloat16* __restrict__ Wl2,
        const float* __restrict__ bias,
        float* __restrict__ Cf, __nv_bfloat16* __restrict__ Cb, int Nrows) {
    __shared__ __align__(16) char smem_raw[SMEM_BF16 * 2];
    __nv_bfloat16* sb = reinterpret_cast<__nv_bfloat16*>(smem_raw);
    __nv_bfloat16* sAh = sb + SM_AH;
    __nv_bfloat16* sAl = sb + SM_AL;
    __nv_bfloat16* sBh = sb + SM_BH;
    __nv_bfloat16* sBl = sb + SM_BL;
    float* sC = reinterpret_cast<float*>(smem_raw);

    const int tid  = threadIdx.x;
    const int lane = tid & 31;
    const int warp = tid >> 5;
    const int wm = warp >> 2;
    const int wn = warp & 3;
    const int row0 = blockIdx.x * 128;

    wmma::fragment<wmma::accumulator, 16, 16, 16, float> acc[4][2];
#pragma unroll
    for (int i = 0; i < 4; i++)
#pragma unroll
        for (int j = 0; j < 2; j++) wmma::fill_fragment(acc[i][j], 0.0f);

    const int nPhase = DUAL ? 2 : 1;
#pragma unroll 1
    for (int ph = 0; ph < nPhase; ph++) {
        const float* A = (ph == 0) ? A1 : A2;
        const __nv_bfloat16* WhP = (ph == 0) ? Wh1 : Wh2;
        const __nv_bfloat16* WlP = (ph == 0) ? Wl1 : Wl2;
        const bool doSplit = (ph == 0);

#pragma unroll 1
        for (int k0 = 0; k0 < 128; k0 += KC) {
#pragma unroll
            for (int it = 0; it < 4; it++) {
                int idx = tid + it * 256;
                int r = idx >> 3;
                int c4 = idx & 7;
                float4 v = make_float4(0.f, 0.f, 0.f, 0.f);
                if (row0 + r < Nrows)
                    v = reinterpret_cast<const float4*>(A + (size_t)(row0 + r) * 128 + k0)[c4];
                __nv_bfloat16 h[4], l[4];
                split_bf16(v.x, h[0], l[0]); split_bf16(v.y, h[1], l[1]);
                split_bf16(v.z, h[2], l[2]); split_bf16(v.w, h[3], l[3]);
                *reinterpret_cast<uint2*>(sAh + r * LDAB + c4 * 4) = *reinterpret_cast<uint2*>(h);
                if (doSplit)
                    *reinterpret_cast<uint2*>(sAl + r * LDAB + c4 * 4) = *reinterpret_cast<uint2*>(l);
            }
#pragma unroll
            for (int it = 0; it < 2; it++) {
                int idx = tid + it * 256;
                int r = idx >> 4;
                int c8 = idx & 15;
                const uint4* srcH = reinterpret_cast<const uint4*>(WhP + (size_t)(k0 + r) * 128) + c8;
                const uint4* srcL = reinterpret_cast<const uint4*>(WlP + (size_t)(k0 + r) * 128) + c8;
                *reinterpret_cast<uint4*>(sBh + r * LDBB + c8 * 8) = __ldg(srcH);
                *reinterpret_cast<uint4*>(sBl + r * LDBB + c8 * 8) = __ldg(srcL);
            }
            __syncthreads();

#pragma unroll
            for (int ks = 0; ks < 2; ks++) {
                const int koff = ks * 16;
                wmma::fragment<wmma::matrix_b, 16, 16, 16, __nv_bfloat16, wmma::row_major> bh[2], bl[2];
#pragma unroll
                for (int j = 0; j < 2; j++) {
                    wmma::load_matrix_sync(bh[j], sBh + koff * LDBB + wn * 32 + j * 16, LDBB);
                    wmma::load_matrix_sync(bl[j], sBl + koff * LDBB + wn * 32 + j * 16, LDBB);
                }
#pragma unroll
                for (int i = 0; i < 4; i++) {
                    wmma::fragment<wmma::matrix_a, 16, 16, 16, __nv_bfloat16, wmma::row_major> ah, al;
                    wmma::load_matrix_sync(ah, sAh + (wm * 64 + i * 16) * LDAB + koff, LDAB);
                    if (doSplit)
                        wmma::load_matrix_sync(al, sAl + (wm * 64 + i * 16) * LDAB + koff, LDAB);
#pragma unroll
                    for (int j = 0; j < 2; j++) {
                        wmma::mma_sync(acc[i][j], ah, bh[j], acc[i][j]);
                        if (doSplit) wmma::mma_sync(acc[i][j], al, bh[j], acc[i][j]);
                        wmma::mma_sync(acc[i][j], ah, bl[j], acc[i][j]);
                    }
                }
            }
            __syncthreads();
        }
    }

#pragma unroll
    for (int half = 0; half < 2; half++) {
        __syncthreads();
        if (wm == half) {
#pragma unroll
            for (int i = 0; i < 4; i++)
#pragma unroll
                for (int j = 0; j < 2; j++)
                    wmma::store_matrix_sync(sC + (i * 16) * LDC + wn * 32 + j * 16,
                                            acc[i][j], LDC, wmma::mem_row_major);
        }
        __syncthreads();
#pragma unroll
        for (int it = 0; it < 8; it++) {
            int idx = tid + it * 256;
            int r = idx >> 5;
            int c4 = idx & 31;
            int grow = row0 + half * 64 + r;
            if (grow < Nrows) {
                float4 o = *reinterpret_cast<float4*>(sC + r * LDC + c4 * 4);
                float4 bv = reinterpret_cast<const float4*>(bias)[c4];
                o.x += bv.x; o.y += bv.y; o.z += bv.z; o.w += bv.w;
                if (OUT_BF16) {
                    __nv_bfloat16 b4[4];
                    b4[0] = __float2bfloat16(o.x); b4[1] = __float2bfloat16(o.y);
                    b4[2] = __float2bfloat16(o.z); b4[3] = __float2bfloat16(o.w);
                    reinterpret_cast<uint2*>(Cb + (size_t)grow * 128)[c4] =
                        *reinterpret_cast<uint2*>(b4);
                } else {
                    reinterpret_cast<float4*>(Cf + (size_t)grow * 128)[c4] = o;
                }
            }
        }
    }
}

// ---------------------------------------------------------------------------
// Edge kernel, packed bf16x2 math: 8 HFMA2 + 2 HMAX2 per edge per lane.
// P rows stay bf16 (no unpack); add_info pre-replicated as bf16x2 quads.
// Run-max kept in bf162; converted to float only at segment-flush.
// atomicMax on int bits valid for nonnegative floats; pooled init 0.
// ---------------------------------------------------------------------------
__device__ __forceinline__ void flush_max2(float* pooled, int seg, int lane,
                                           __nv_bfloat162 v01, __nv_bfloat162 v23) {
    if (seg < 0) return;
    float2 f01 = __bfloat1622float2(v01);
    float2 f23 = __bfloat1622float2(v23);
    int* p = reinterpret_cast<int*>(pooled + (size_t)seg * 128 + lane * 4);
    if (f01.x > 0.f) atomicMax(p + 0, __float_as_int(f01.x));
    if (f01.y > 0.f) atomicMax(p + 1, __float_as_int(f01.y));
    if (f23.x > 0.f) atomicMax(p + 2, __float_as_int(f23.x));
    if (f23.y > 0.f) atomicMax(p + 3, __float_as_int(f23.y));
}

constexpr int PF = 8;

__global__ __launch_bounds__(256) void edge_kernel(
        const uint2* __restrict__ P2,      // N x 32 uint2 (bf16 rows)
        const uint4* __restrict__ aib,     // E replicated-bf162 quads
        const int* __restrict__ nb, const int* __restrict__ seg,
        const float* __restrict__ Wba, float* __restrict__ pooled, int E) {
    // Weights as bf162 pairs: wsh2[row][lane][half] covers cols [4*lane,4*lane+4)
    __shared__ __nv_bfloat162 wsh2[4][32][2];
    const int tid = threadIdx.x;
    if (tid < 128) {
        int r = tid >> 5, c = tid & 31;
        float4 w = reinterpret_cast<const float4*>(Wba)[tid];
        wsh2[r][c][0] = __floats2bfloat162_rn(w.x, w.y);
        wsh2[r][c][1] = __floats2bfloat162_rn(w.z, w.w);
    }
    __syncthreads();

    const int lane = tid & 31;
    const int warp = tid >> 5;
    const __nv_bfloat162 w0a = wsh2[0][lane][0], w0b = wsh2[0][lane][1];
    const __nv_bfloat162 w1a = wsh2[1][lane][0], w1b = wsh2[1][lane][1];
    const __nv_bfloat162 w2a = wsh2[2][lane][0], w2b = wsh2[2][lane][1];
    const __nv_bfloat162 w3a = wsh2[3][lane][0], w3b = wsh2[3][lane][1];
    const __nv_bfloat162 zero2 = __float2bfloat162_rn(0.f);

    const int base = (blockIdx.x * (blockDim.x >> 5) + warp) * 32;
    if (base >= E) return;
    const int cnt = min(32, E - base);

    __nv_bfloat162 vmax01 = zero2, vmax23 = zero2;
    int cur = -1;

    if (cnt == 32) {
        uint2 praw[PF];
#pragma unroll
        for (int i = 0; i < PF; i++) {
            int n = __ldg(nb + base + i);
            praw[i] = __ldg(P2 + (size_t)n * 32 + lane);
        }
#pragma unroll
        for (int i = 0; i < 32; i++) {
            int e = base + i;
            int s = __ldg(seg + e);
            uint4 ar = __ldg(aib + e);
            __nv_bfloat162 ax = *reinterpret_cast<__nv_bfloat162*>(&ar.x);
            __nv_bfloat162 ay = *reinterpret_cast<__nv_bfloat162*>(&ar.y);
            __nv_bfloat162 az = *reinterpret_cast<__nv_bfloat162*>(&ar.z);
            __nv_bfloat162 aw = *reinterpret_cast<__nv_bfloat162*>(&ar.w);
            uint2 raw = praw[i & (PF - 1)];
            __nv_bfloat162 h01 = *reinterpret_cast<__nv_bfloat162*>(&raw.x);
            __nv_bfloat162 h23 = *reinterpret_cast<__nv_bfloat162*>(&raw.y);

            h01 = __hfma2(ax, w0a, h01); h23 = __hfma2(ax, w0b, h23);
            h01 = __hfma2(ay, w1a, h01); h23 = __hfma2(ay, w1b, h23);
            h01 = __hfma2(az, w2a, h01); h23 = __hfma2(az, w2b, h23);
            h01 = __hfma2(aw, w3a, h01); h23 = __hfma2(aw, w3b, h23);

            if (s != cur) {             // warp-uniform branch
                flush_max2(pooled, cur, lane, vmax01, vmax23);
                cur = s;
                vmax01 = __hmax2(h01, zero2);
                vmax23 = __hmax2(h23, zero2);
            } else {                    // vmax >= 0 -> relu folded into max
                vmax01 = __hmax2(vmax01, h01);
                vmax23 = __hmax2(vmax23, h23);
            }
            if (i + PF < 32) {
                int n = __ldg(nb + base + i + PF);
                praw[i & (PF - 1)] = __ldg(P2 + (size_t)n * 32 + lane);
            }
        }
    } else {
        for (int i = 0; i < cnt; i++) {
            int e = base + i;
            int s = __ldg(seg + e);
            int n = __ldg(nb + e);
            uint4 ar = __ldg(aib + e);
            __nv_bfloat162 ax = *reinterpret_cast<__nv_bfloat162*>(&ar.x);
            __nv_bfloat162 ay = *reinterpret_cast<__nv_bfloat162*>(&ar.y);
            __nv_bfloat162 az = *reinterpret_cast<__nv_bfloat162*>(&ar.z);
            __nv_bfloat162 aw = *reinterpret_cast<__nv_bfloat162*>(&ar.w);
            uint2 raw = __ldg(P2 + (size_t)n * 32 + lane);
            __nv_bfloat162 h01 = *reinterpret_cast<__nv_bfloat162*>(&raw.x);
            __nv_bfloat162 h23 = *reinterpret_cast<__nv_bfloat162*>(&raw.y);
            h01 = __hfma2(ax, w0a, h01); h23 = __hfma2(ax, w0b, h23);
            h01 = __hfma2(ay, w1a, h01); h23 = __hfma2(ay, w1b, h23);
            h01 = __hfma2(az, w2a, h01); h23 = __hfma2(az, w2b, h23);
            h01 = __hfma2(aw, w3a, h01); h23 = __hfma2(aw, w3b, h23);
            if (s != cur) {
                flush_max2(pooled, cur, lane, vmax01, vmax23);
                cur = s;
                vmax01 = __hmax2(h01, zero2);
                vmax23 = __hmax2(h23, zero2);
            } else {
                vmax01 = __hmax2(vmax01, h01);
                vmax23 = __hmax2(vmax23, h23);
            }
        }
    }
    flush_max2(pooled, cur, lane, vmax01, vmax23);
}

// ---------------------------------------------------------------------------
// Final: out[n] = interp[n]@Wf + pool0[n]@wf0 + pool1[n]@wf1 + cf
// ---------------------------------------------------------------------------
__global__ void final_kernel(const float* __restrict__ interp,
                             const float* __restrict__ pool0,
                             const float* __restrict__ pool1,
                             const float* __restrict__ Wf,
                             const float* __restrict__ wf0,
                             const float* __restrict__ wf1,
                             const float* __restrict__ cf,
                             float* __restrict__ out, int N) {
    int gwarp = (blockIdx.x * blockDim.x + threadIdx.x) >> 5;
    int lane = threadIdx.x & 31;
    if (gwarp >= N) return;
    float4 xv = reinterpret_cast<const float4*>(interp + (size_t)gwarp * 128)[lane];
    float4 p0 = reinterpret_cast<const float4*>(pool0 + (size_t)gwarp * 128)[lane];
    float4 p1 = reinterpret_cast<const float4*>(pool1 + (size_t)gwarp * 128)[lane];
    float4 wv = reinterpret_cast<const float4*>(Wf)[lane];
    float4 v0 = reinterpret_cast<const float4*>(wf0)[lane];
    float4 v1 = reinterpret_cast<const float4*>(wf1)[lane];
    float s = xv.x * wv.x + xv.y * wv.y + xv.z * wv.z + xv.w * wv.w
            + p0.x * v0.x + p0.y * v0.y + p0.z * v0.z + p0.w * v0.w
            + p1.x * v1.x + p1.y * v1.y + p1.z * v1.z + p1.w * v1.w;
#pragma unroll
    for (int o = 16; o; o >>= 1) s += __shfl_xor_sync(0xFFFFFFFFu, s, o);
    if (lane == 0) out[gwarp] = s + cf[0];
}

// ---------------------------------------------------------------------------
extern "C" void kernel_launch(void* const* d_in, const int* in_sizes, int n_in,
                              void* d_out, int out_size) {
    const float* interpolated = (const float*)d_in[0];
    const float* add_info     = (const float*)d_in[1];
    const int*   nb           = (const int*)d_in[2];
    const int*   seg          = (const int*)d_in[3];
    const float* Wb0 = (const float*)d_in[4];
    const float* bb0 = (const float*)d_in[5];
    const float* Wo0 = (const float*)d_in[6];
    const float* bo0 = (const float*)d_in[7];
    const float* Wb1 = (const float*)d_in[8];
    const float* bb1 = (const float*)d_in[9];
    const float* Wo1 = (const float*)d_in[10];
    const float* bo1 = (const float*)d_in[11];
    const float* Wf  = (const float*)d_in[12];
    const float* bf  = (const float*)d_in[13];

    const int N = in_sizes[0] / 128;
    const int E = in_sizes[2];

    __nv_bfloat16 *Pb, *Wh, *Wl;
    float *pool0, *pool1, *Wc10, *wf0, *wf1, *c1, *cf;
    uint4* aib;
    cudaGetSymbolAddress((void**)&Pb,    g_Pb);
    cudaGetSymbolAddress((void**)&pool0, g_pool0);
    cudaGetSymbolAddress((void**)&pool1, g_pool1);
    cudaGetSymbolAddress((void**)&aib,   g_aib);
    cudaGetSymbolAddress((void**)&Wh,    g_Wh);
    cudaGetSymbolAddress((void**)&Wl,    g_Wl);
    cudaGetSymbolAddress((void**)&Wc10,  g_Wc10);
    cudaGetSymbolAddress((void**)&wf0,   g_wf0);
    cudaGetSymbolAddress((void**)&wf1,   g_wf1);
    cudaGetSymbolAddress((void**)&c1,    g_c1);
    cudaGetSymbolAddress((void**)&cf,    g_cf);

    const int gemmGrid = (N + 127) / 128;
    const int edgeGrid = (E + 255) / 256;
    const size_t poolBytes = (size_t)N * 128 * sizeof(float);
    const uint2* P2 = (const uint2*)Pb;
    const int WM = 128 * 128;

    // Prep (independent of main chain until first consumer).
    prepA_kernel<<<66, 256>>>(Wo0, Wb1, Wo1, Wf, bb1, bo0, bo1, bf,
                              Wc10, wf0, wf1, c1, cf);
    split_w_kernel<<<48, 256>>>(Wb0, Wb1, Wc10, Wh, Wl);
    cvt_ai_kernel<<<(E + 255) / 256, 256>>>((const float4*)add_info, aib, E);
    cudaMemsetAsync(pool0, 0, poolBytes);
    cudaMemsetAsync(pool1, 0, poolBytes);

    // Block 0: P0 = interp@Wb0top + bb0
    gemm_kernel<true, false><<<gemmGrid, 256>>>(
        interpolated, Wh + 0 * WM, Wl + 0 * WM,
        nullptr, nullptr, nullptr, bb0, nullptr, Pb, N);
    edge_kernel<<<edgeGrid, 256>>>(P2, aib, nb, seg, Wb0 + 128 * 128, pool0, E);

    // Mid (fused): P1 = interp@Wb1top + pool0@Wc10 + c1
    gemm_kernel<true, true><<<gemmGrid, 256>>>(
        interpolated, Wh + 1 * WM, Wl + 1 * WM,
        pool0, Wh + 2 * WM, Wl + 2 * WM, c1, nullptr, Pb, N);
    edge_kernel<<<edgeGrid, 256>>>(P2, aib, nb, seg, Wb1 + 128 * 128, pool1, E);

    // Final: out = interp@Wf + pool0@wf0 + pool1@wf1 + cf
    final_kernel<<<(N * 32 + 255) / 256, 256>>>(
        interpolated, pool0, pool1, Wf, wf0, wf1, cf, (float*)d_out, N);
}